// round 1
// baseline (speedup 1.0000x reference)
#include <cuda_runtime.h>
#include <cstdint>
#include <cstddef>

namespace cfg {
constexpr int B = 4;
constexpr int T = 512;
constexpr int H = 768;
constexpr int N = 256;
constexpr int S = 16;
constexpr int NERD = 32;
constexpr int D = 800;          // H + NERD
constexpr int R = 15;
constexpr int NE = 64;
constexpr int MM = 8;
constexpr int P = 1024;
constexpr int E = 4096;
constexpr int OUT = 97;
constexpr int EE = 1600;        // 2*D
constexpr int HID = 3200;       // 2*EE
constexpr int KG = 12800;       // 16*D  ([S_0..S_14 | h])
constexpr int KSPLIT = 12000;   // R*D
}

// ---------------- scratch (device globals; no runtime allocation) ----------------
__device__ float g_docproj[cfg::B * cfg::D];
__device__ float g_h0[cfg::B * cfg::N * cfg::D];
__device__ float g_h1[cfg::B * cfg::N * cfg::D];
__device__ float g_h2[cfg::B * cfg::N * cfg::D];
__device__ float g_A[(size_t)cfg::B * cfg::N * 16 * cfg::D];          // 52 MB
__device__ float g_ent[cfg::B * cfg::NE * cfg::EE];
__device__ float g_entA[cfg::B * cfg::NE * cfg::HID];
__device__ float g_entB[cfg::B * cfg::NE * cfg::HID];
__device__ float g_nl[(size_t)cfg::B * cfg::P * cfg::HID];            // 52 MB
__device__ float g_hidden[(size_t)cfg::B * cfg::P * cfg::HID];        // 52 MB

// ---------------- doc projection: relu(cls @ doc_W + doc_b) ----------------
__global__ void k_docproj(const float* __restrict__ cls, const float* __restrict__ W,
                          const float* __restrict__ bvec, float* __restrict__ out) {
    using namespace cfg;
    int b = blockIdx.y;
    int d = blockIdx.x * blockDim.x + threadIdx.x;
    if (d >= D) return;
    float acc = bvec[d];
    const float* c = cls + b * H;
    for (int h = 0; h < H; h++) acc = fmaf(c[h], W[(size_t)h * D + d], acc);
    out[b * D + d] = fmaxf(acc, 0.f);
}

// ---------------- node features h0 ----------------
__global__ void k_node(const float* __restrict__ token, const float* __restrict__ cls,
                       const int* __restrict__ pos, const float* __restrict__ smask,
                       const int* __restrict__ ner, const float* __restrict__ nmask,
                       const int* __restrict__ ment, const float* __restrict__ nerEmb,
                       const float* __restrict__ docproj, float* __restrict__ h0) {
    using namespace cfg;
    const int n = blockIdx.x, b = blockIdx.y;
    __shared__ int sp[S];
    __shared__ float sm[S];
    int tid = threadIdx.x;
    if (tid < S) {
        sp[tid] = pos[(b * N + n) * S + tid];
        sm[tid] = smask[(b * N + n) * S + tid];
    }
    __syncthreads();
    float* dst = h0 + (size_t)(b * N + n) * D;
    if (n == ment[b]) {   // x.at[m].set(doc_proj)
        for (int d = tid; d < D; d += blockDim.x) dst[d] = docproj[b * D + d];
        return;
    }
    float den = 0.1f;
#pragma unroll
    for (int s = 0; s < S; s++) den += sm[s];
    float nm = nmask[b * N + n];
    int nerIdx = ner[b * N + n];
    for (int d = tid; d < D; d += blockDim.x) {
        float v;
        if (d < H) {
            float acc = 0.f;
#pragma unroll
            for (int s = 0; s < S; s++)
                acc = fmaf(token[((size_t)b * T + sp[s]) * H + d], sm[s], acc);
            v = acc / den + cls[b * H + d];
        } else {
            v = nerEmb[nerIdx * NERD + (d - H)];
        }
        dst[d] = v * nm;
    }
}

// ---------------- init A buffer: slots 0..14 = 0, slot 15 = h ----------------
__global__ void k_initA(const float* __restrict__ hin, float* __restrict__ A) {
    using namespace cfg;
    size_t idx = (size_t)blockIdx.x * blockDim.x + threadIdx.x;   // exact grid
    int d = (int)(idx % D);
    size_t rest = idx / D;
    int r = (int)(rest & 15);
    size_t bn = rest >> 4;
    A[idx] = (r == 15) ? hin[bn * D + d] : 0.f;
}

// ---------------- edge scatter: A[b,dst,rel,:] += h[b,src,:] ----------------
__global__ void k_scatter(const float* __restrict__ hin, const int* __restrict__ src,
                          const int* __restrict__ dst, const int* __restrict__ rel,
                          float* __restrict__ A) {
    using namespace cfg;
    int e = blockIdx.x, b = blockIdx.y;
    int sIdx = src[b * E + e];
    int dIdx = dst[b * E + e];
    int r = rel[b * E + e];
    const float* hrow = hin + (size_t)(b * N + sIdx) * D;
    float* arow = A + ((size_t)(b * N + dIdx) * 16 + r) * D;
    for (int d = threadIdx.x; d < D; d += blockDim.x)
        atomicAdd(&arow[d], hrow[d]);
}

// ---------------- tiled SGEMM, 128x64x16, 256 thr, 8x4/thread ----------------
// MODE 0: GNN   -> relu(acc + bias[col])
// MODE 1: plain -> acc
// MODE 2: pair  -> relu(acc + entA[p0,col] + entB[p1,col] + bias[col])
template <int MODE>
__global__ void __launch_bounds__(256)
k_gemm(const float* __restrict__ A, int K, int Ncol, int Ksplit,
       const float* __restrict__ W0, const float* __restrict__ Wsf,
       const float* __restrict__ bias, float* __restrict__ C,
       const float* __restrict__ gA, const float* __restrict__ gB,
       const int* __restrict__ pairs) {
    using namespace cfg;
    constexpr int BM = 128, BN = 64, BK = 16;
    __shared__ __align__(16) float As[BK][BM + 4];   // +4 pad keeps 16B-aligned rows
    __shared__ __align__(16) float Bs[BK][BN];
    const int tid = threadIdx.x;
    const int ty = tid >> 4;      // 0..15 (M dir, 8 rows each)
    const int tx = tid & 15;      // 0..15 (N dir, 4 cols each)
    const int bm0 = blockIdx.y * BM;
    const int bn0 = blockIdx.x * BN;
    float acc[8][4] = {};

    const float* Abase = A + (size_t)bm0 * K;

    for (int k0 = 0; k0 < K; k0 += BK) {
        // A tile: 128x16 = 512 float4, 2 per thread, transposed into As[k][m]
#pragma unroll
        for (int t = 0; t < 2; t++) {
            int f = tid + t * 256;
            int m = f >> 2;
            int kq = f & 3;
            const float4 v = *reinterpret_cast<const float4*>(Abase + (size_t)m * K + k0 + kq * 4);
            As[kq * 4 + 0][m] = v.x;
            As[kq * 4 + 1][m] = v.y;
            As[kq * 4 + 2][m] = v.z;
            As[kq * 4 + 3][m] = v.w;
        }
        // B tile: 16x64 = 256 float4, 1 per thread; weight row may come from W0 or Wsf
        {
            int kk = tid >> 4;
            int nq = tid & 15;
            int kg = k0 + kk;
            const float* wrow = (kg < Ksplit) ? (W0 + (size_t)kg * Ncol)
                                              : (Wsf + (size_t)(kg - Ksplit) * Ncol);
            int n = bn0 + nq * 4;
            float4 v;
            if (n + 3 < Ncol) {
                v = *reinterpret_cast<const float4*>(wrow + n);
            } else {
                v.x = (n + 0 < Ncol) ? wrow[n + 0] : 0.f;
                v.y = (n + 1 < Ncol) ? wrow[n + 1] : 0.f;
                v.z = (n + 2 < Ncol) ? wrow[n + 2] : 0.f;
                v.w = (n + 3 < Ncol) ? wrow[n + 3] : 0.f;
            }
            *reinterpret_cast<float4*>(&Bs[kk][nq * 4]) = v;
        }
        __syncthreads();
#pragma unroll
        for (int kk = 0; kk < BK; kk++) {
            float a[8], bv[4];
            float4 a0 = *reinterpret_cast<const float4*>(&As[kk][ty * 8]);
            float4 a1 = *reinterpret_cast<const float4*>(&As[kk][ty * 8 + 4]);
            a[0] = a0.x; a[1] = a0.y; a[2] = a0.z; a[3] = a0.w;
            a[4] = a1.x; a[5] = a1.y; a[6] = a1.z; a[7] = a1.w;
            float4 bb = *reinterpret_cast<const float4*>(&Bs[kk][tx * 4]);
            bv[0] = bb.x; bv[1] = bb.y; bv[2] = bb.z; bv[3] = bb.w;
#pragma unroll
            for (int i = 0; i < 8; i++)
#pragma unroll
                for (int j = 0; j < 4; j++)
                    acc[i][j] = fmaf(a[i], bv[j], acc[i][j]);
        }
        __syncthreads();
    }

#pragma unroll
    for (int i = 0; i < 8; i++) {
        int row = bm0 + ty * 8 + i;
#pragma unroll
        for (int j = 0; j < 4; j++) {
            int col = bn0 + tx * 4 + j;
            if (col >= Ncol) continue;
            float v = acc[i][j];
            if (MODE == 0) {
                v = fmaxf(v + bias[col], 0.f);
            } else if (MODE == 2) {
                int b = row >> 10;            // row = b*P + p, P = 1024
                int p = row & 1023;
                int p0 = pairs[(b * P + p) * 2 + 0];
                int p1 = pairs[(b * P + p) * 2 + 1];
                v += gA[(size_t)(b * NE + p0) * HID + col] +
                     gB[(size_t)(b * NE + p1) * HID + col] + bias[col];
                v = fmaxf(v, 0.f);
            }
            C[(size_t)row * Ncol + col] = v;
        }
    }
}

// ---------------- entity pooling over mentions (with zero row at id 0) ----------------
__global__ void k_ent(const float* __restrict__ h1, const float* __restrict__ h2,
                      const int* __restrict__ e2m, const float* __restrict__ e2mask,
                      float* __restrict__ ent) {
    using namespace cfg;
    int i = blockIdx.x, b = blockIdx.y;
    __shared__ int idxs[MM];
    __shared__ float mk[MM];
    int tid = threadIdx.x;
    if (tid < MM) {
        idxs[tid] = e2m[(b * NE + i) * MM + tid];
        mk[tid] = e2mask[(b * NE + i) * MM + tid];
    }
    __syncthreads();
    float den = 1e-7f;
#pragma unroll
    for (int j = 0; j < MM; j++) den += mk[j];
    for (int c = tid; c < EE; c += blockDim.x) {
        float acc = 0.f;
#pragma unroll
        for (int j = 0; j < MM; j++) {
            int id = idxs[j];
            if (id > 0) {
                float v = (c < D) ? h1[(size_t)(b * N + id - 1) * D + c]
                                  : h2[(size_t)(b * N + id - 1) * D + (c - D)];
                acc = fmaf(v, mk[j], acc);
            }
        }
        ent[(size_t)(b * NE + i) * EE + c] = acc / den;
    }
}

// ---------------- per-pair nonlinear features [|hf-tf|, hf*tf] ----------------
__global__ void k_nl(const float* __restrict__ ent, const int* __restrict__ pairs,
                     float* __restrict__ nl) {
    using namespace cfg;
    int p = blockIdx.x, b = blockIdx.y;
    int p0 = pairs[(b * P + p) * 2 + 0];
    int p1 = pairs[(b * P + p) * 2 + 1];
    const float* hf = ent + (size_t)(b * NE + p0) * EE;
    const float* tf = ent + (size_t)(b * NE + p1) * EE;
    float* dst = nl + ((size_t)b * P + p) * HID;
    for (int c = threadIdx.x; c < EE; c += blockDim.x) {
        float a = hf[c], t = tf[c];
        dst[c] = fabsf(a - t);
        dst[EE + c] = a * t;
    }
}

// ---------------- final GEMM: hidden(4096x3200) @ W2(3200x97) + b2 ----------------
__global__ void __launch_bounds__(128)
k_out(const float* __restrict__ hid, const float* __restrict__ W2,
      const float* __restrict__ b2, float* __restrict__ out) {
    using namespace cfg;
    constexpr int RPB = 8, KC = 320;
    __shared__ float sh[RPB][KC];
    int row0 = blockIdx.x * RPB;
    int tid = threadIdx.x;
    float acc[RPB] = {};
    for (int k0 = 0; k0 < HID; k0 += KC) {
        for (int f = tid; f < RPB * KC; f += 128) {
            int r = f / KC, k = f % KC;
            sh[r][k] = hid[(size_t)(row0 + r) * HID + k0 + k];
        }
        __syncthreads();
        if (tid < OUT) {
            for (int kk = 0; kk < KC; kk++) {
                float w = W2[(size_t)(k0 + kk) * OUT + tid];
#pragma unroll
                for (int r = 0; r < RPB; r++) acc[r] = fmaf(sh[r][kk], w, acc[r]);
            }
        }
        __syncthreads();
    }
    if (tid < OUT) {
        float bb = b2[tid];
#pragma unroll
        for (int r = 0; r < RPB; r++)
            out[(size_t)(row0 + r) * OUT + tid] = acc[r] + bb;
    }
}

// ---------------- launch ----------------
extern "C" void kernel_launch(void* const* d_in, const int* in_sizes, int n_in,
                              void* d_out, int out_size) {
    using namespace cfg;
    const float* token     = (const float*)d_in[0];
    const float* cls       = (const float*)d_in[1];
    const int*   span_pos  = (const int*)d_in[2];
    const float* span_mask = (const float*)d_in[3];
    const int*   node_ner  = (const int*)d_in[4];
    const float* node_mask = (const float*)d_in[5];
    const int*   e2m       = (const int*)d_in[6];
    const float* e2m_mask  = (const float*)d_in[7];
    const int*   ent_pair  = (const int*)d_in[8];
    const int*   edge_src  = (const int*)d_in[9];
    const int*   edge_dst  = (const int*)d_in[10];
    const int*   edge_rel  = (const int*)d_in[11];
    const int*   ment_num  = (const int*)d_in[12];
    const float* nerEmb    = (const float*)d_in[13];
    const float* doc_W     = (const float*)d_in[14];
    const float* doc_b     = (const float*)d_in[15];
    const float* W_rel     = (const float*)d_in[16];
    const float* W_self    = (const float*)d_in[17];
    const float* gnn_b     = (const float*)d_in[18];
    const float* W1        = (const float*)d_in[19];
    const float* b1        = (const float*)d_in[20];
    const float* W2        = (const float*)d_in[21];
    const float* b2        = (const float*)d_in[22];
    float* out = (float*)d_out;
    (void)in_sizes; (void)n_in; (void)out_size;

    float *pdoc, *ph0, *ph1, *ph2, *pA, *pent, *pentA, *pentB, *pnl, *phid;
    cudaGetSymbolAddress((void**)&pdoc,  g_docproj);
    cudaGetSymbolAddress((void**)&ph0,   g_h0);
    cudaGetSymbolAddress((void**)&ph1,   g_h1);
    cudaGetSymbolAddress((void**)&ph2,   g_h2);
    cudaGetSymbolAddress((void**)&pA,    g_A);
    cudaGetSymbolAddress((void**)&pent,  g_ent);
    cudaGetSymbolAddress((void**)&pentA, g_entA);
    cudaGetSymbolAddress((void**)&pentB, g_entB);
    cudaGetSymbolAddress((void**)&pnl,   g_nl);
    cudaGetSymbolAddress((void**)&phid,  g_hidden);

    // 1) doc projection + node features
    k_docproj<<<dim3((D + 255) / 256, B), 256>>>(cls, doc_W, doc_b, pdoc);
    k_node<<<dim3(N, B), 256>>>(token, cls, span_pos, span_mask, node_ner, node_mask,
                                ment_num, nerEmb, pdoc, ph0);

    const size_t Atotal = (size_t)B * N * 16 * D;   // 13,107,200, %256 == 0
    const int initBlocks = (int)(Atotal / 256);

    // 2) GNN layer 0
    k_initA<<<initBlocks, 256>>>(ph0, pA);
    k_scatter<<<dim3(E, B), 256>>>(ph0, edge_src, edge_dst, edge_rel, pA);
    k_gemm<0><<<dim3((D + 63) / 64, (B * N) / 128), 256>>>(
        pA, KG, D, KSPLIT, W_rel, W_self, gnn_b, ph1, nullptr, nullptr, nullptr);

    // 3) GNN layer 1
    k_initA<<<initBlocks, 256>>>(ph1, pA);
    k_scatter<<<dim3(E, B), 256>>>(ph1, edge_src, edge_dst, edge_rel, pA);
    k_gemm<0><<<dim3((D + 63) / 64, (B * N) / 128), 256>>>(
        pA, KG, D, KSPLIT, W_rel + (size_t)R * D * D, W_self + (size_t)D * D,
        gnn_b + D, ph2, nullptr, nullptr, nullptr);

    // 4) entity pooling
    k_ent<<<dim3(NE, B), 256>>>(ph1, ph2, e2m, e2m_mask, pent);

    // 5) linear halves of pair MLP: entA = ent@W1[0:EE], entB = ent@W1[EE:2EE]
    k_gemm<1><<<dim3(HID / 64, (B * NE) / 128), 256>>>(
        pent, EE, HID, EE, W1, W1, nullptr, pentA, nullptr, nullptr, nullptr);
    k_gemm<1><<<dim3(HID / 64, (B * NE) / 128), 256>>>(
        pent, EE, HID, EE, W1 + (size_t)EE * HID, W1, nullptr, pentB,
        nullptr, nullptr, nullptr);

    // 6) nonlinear pair features + big GEMM with fused gather epilogue
    k_nl<<<dim3(P, B), 256>>>(pent, ent_pair, pnl);
    k_gemm<2><<<dim3(HID / 64, (B * P) / 128), 256>>>(
        pnl, HID, HID, HID, W1 + (size_t)2 * EE * HID, W1, b1, phid,
        pentA, pentB, ent_pair);

    // 7) output layer
    k_out<<<(B * P) / 8, 128>>>(phid, W2, b2, out);
}

// round 2
// speedup vs baseline: 1.0309x; 1.0309x over previous
#include <cuda_runtime.h>
#include <cstdint>
#include <cstddef>

namespace cfg {
constexpr int B = 4;
constexpr int T = 512;
constexpr int H = 768;
constexpr int N = 256;
constexpr int S = 16;
constexpr int NERD = 32;
constexpr int D = 800;          // H + NERD
constexpr int R = 15;
constexpr int NE = 64;
constexpr int MM = 8;
constexpr int P = 1024;
constexpr int E = 4096;
constexpr int OUT = 97;
constexpr int EE = 1600;        // 2*D
constexpr int HID = 3200;       // 2*EE
constexpr int KG = 12800;       // 16*D  ([S_0..S_14 | h])
constexpr int KSPLIT = 12000;   // R*D
}

// ---------------- scratch (device globals; no runtime allocation) ----------------
__device__ float g_docproj[cfg::B * cfg::D];
__device__ float g_h0[cfg::B * cfg::N * cfg::D];
__device__ float g_h1[cfg::B * cfg::N * cfg::D];
__device__ float g_h2[cfg::B * cfg::N * cfg::D];
__device__ float g_A[(size_t)cfg::B * cfg::N * 16 * cfg::D];          // 52 MB
__device__ float g_ent[cfg::B * cfg::NE * cfg::EE];
__device__ float g_entA[cfg::B * cfg::NE * cfg::HID];
__device__ float g_entB[cfg::B * cfg::NE * cfg::HID];
__device__ float g_nl[(size_t)cfg::B * cfg::P * cfg::HID];            // 52 MB
__device__ float g_hidden[(size_t)cfg::B * cfg::P * cfg::HID];        // 52 MB

// packed f32x2 helpers
__device__ __forceinline__ unsigned long long bcast_f32x2(float x) {
    unsigned long long r;
    asm("mov.b64 %0, {%1, %1};" : "=l"(r) : "f"(x));
    return r;
}
__device__ __forceinline__ void fma_f32x2(unsigned long long& acc,
                                          unsigned long long a,
                                          unsigned long long b) {
    asm("fma.rn.f32x2 %0, %1, %2, %0;" : "+l"(acc) : "l"(a), "l"(b));
}

// ---------------- doc projection: relu(cls @ doc_W + doc_b) ----------------
__global__ void k_docproj(const float* __restrict__ cls, const float* __restrict__ W,
                          const float* __restrict__ bvec, float* __restrict__ out) {
    using namespace cfg;
    int b = blockIdx.y;
    int d = blockIdx.x * blockDim.x + threadIdx.x;
    if (d >= D) return;
    float acc = bvec[d];
    const float* c = cls + b * H;
    for (int h = 0; h < H; h++) acc = fmaf(c[h], W[(size_t)h * D + d], acc);
    out[b * D + d] = fmaxf(acc, 0.f);
}

// ---------------- node features h0 ----------------
__global__ void k_node(const float* __restrict__ token, const float* __restrict__ cls,
                       const int* __restrict__ pos, const float* __restrict__ smask,
                       const int* __restrict__ ner, const float* __restrict__ nmask,
                       const int* __restrict__ ment, const float* __restrict__ nerEmb,
                       const float* __restrict__ docproj, float* __restrict__ h0) {
    using namespace cfg;
    const int n = blockIdx.x, b = blockIdx.y;
    __shared__ int sp[S];
    __shared__ float sm[S];
    int tid = threadIdx.x;
    if (tid < S) {
        sp[tid] = pos[(b * N + n) * S + tid];
        sm[tid] = smask[(b * N + n) * S + tid];
    }
    __syncthreads();
    float* dst = h0 + (size_t)(b * N + n) * D;
    if (n == ment[b]) {   // x.at[m].set(doc_proj)
        for (int d = tid; d < D; d += blockDim.x) dst[d] = docproj[b * D + d];
        return;
    }
    float den = 0.1f;
#pragma unroll
    for (int s = 0; s < S; s++) den += sm[s];
    float nm = nmask[b * N + n];
    int nerIdx = ner[b * N + n];
    for (int d = tid; d < D; d += blockDim.x) {
        float v;
        if (d < H) {
            float acc = 0.f;
#pragma unroll
            for (int s = 0; s < S; s++)
                acc = fmaf(token[((size_t)b * T + sp[s]) * H + d], sm[s], acc);
            v = acc / den + cls[b * H + d];
        } else {
            v = nerEmb[nerIdx * NERD + (d - H)];
        }
        dst[d] = v * nm;
    }
}

// ---------------- init A buffer: slots 0..14 = 0, slot 15 = h ----------------
__global__ void k_initA(const float* __restrict__ hin, float* __restrict__ A) {
    using namespace cfg;
    size_t idx = (size_t)blockIdx.x * blockDim.x + threadIdx.x;   // exact grid
    int d = (int)(idx % D);
    size_t rest = idx / D;
    int r = (int)(rest & 15);
    size_t bn = rest >> 4;
    A[idx] = (r == 15) ? hin[bn * D + d] : 0.f;
}

// ---------------- edge scatter: A[b,dst,rel,:] += h[b,src,:] ----------------
__global__ void k_scatter(const float* __restrict__ hin, const int* __restrict__ src,
                          const int* __restrict__ dst, const int* __restrict__ rel,
                          float* __restrict__ A) {
    using namespace cfg;
    int e = blockIdx.x, b = blockIdx.y;
    int sIdx = src[b * E + e];
    int dIdx = dst[b * E + e];
    int r = rel[b * E + e];
    const float* hrow = hin + (size_t)(b * N + sIdx) * D;
    float* arow = A + ((size_t)(b * N + dIdx) * 16 + r) * D;
    for (int d = threadIdx.x; d < D; d += blockDim.x)
        atomicAdd(&arow[d], hrow[d]);
}

// ---------------- tiled SGEMM, 128x64x16, 256 thr, 8x4/thread, FFMA2 ----------------
// MODE 0: GNN   -> relu(acc + bias[col])
// MODE 1: plain -> acc
// MODE 2: pair  -> relu(acc + entA[p0,col] + entB[p1,col] + bias[col])
template <int MODE>
__global__ void __launch_bounds__(256)
k_gemm(const float* __restrict__ A, int K, int Ncol, int Ksplit,
       const float* __restrict__ W0, const float* __restrict__ Wsf,
       const float* __restrict__ bias, float* __restrict__ C,
       const float* __restrict__ gA, const float* __restrict__ gB,
       const int* __restrict__ pairs) {
    using namespace cfg;
    constexpr int BM = 128, BN = 64, BK = 16;
    __shared__ __align__(16) float As[BK][BM + 4];   // row stride 132 fl = 528 B (16B-aligned)
    __shared__ __align__(16) float Bs[BK][BN];
    const int tid = threadIdx.x;
    const int ty = tid >> 4;      // 0..15 (M dir, 8 rows each)
    const int tx = tid & 15;      // 0..15 (N dir, 4 cols each)
    const int bm0 = blockIdx.y * BM;
    const int bn0 = blockIdx.x * BN;

    // acc2[i2][j]: packed row-pairs (rows 2*i2, 2*i2+1) x 4 cols
    unsigned long long acc2[4][4] = {};

    const float* Abase = A + (size_t)bm0 * K;

    for (int k0 = 0; k0 < K; k0 += BK) {
        // A tile: 128x16 = 512 float4, 2 per thread, transposed into As[k][m]
#pragma unroll
        for (int t = 0; t < 2; t++) {
            int f = tid + t * 256;
            int m = f >> 2;
            int kq = f & 3;
            const float4 v = *reinterpret_cast<const float4*>(Abase + (size_t)m * K + k0 + kq * 4);
            As[kq * 4 + 0][m] = v.x;
            As[kq * 4 + 1][m] = v.y;
            As[kq * 4 + 2][m] = v.z;
            As[kq * 4 + 3][m] = v.w;
        }
        // B tile: 16x64 = 256 float4, 1 per thread; weight row may come from W0 or Wsf
        {
            int kk = tid >> 4;
            int nq = tid & 15;
            int kg = k0 + kk;
            const float* wrow = (kg < Ksplit) ? (W0 + (size_t)kg * Ncol)
                                              : (Wsf + (size_t)(kg - Ksplit) * Ncol);
            int n = bn0 + nq * 4;
            float4 v;
            if (n + 3 < Ncol) {
                v = *reinterpret_cast<const float4*>(wrow + n);
            } else {
                v.x = (n + 0 < Ncol) ? wrow[n + 0] : 0.f;
                v.y = (n + 1 < Ncol) ? wrow[n + 1] : 0.f;
                v.z = (n + 2 < Ncol) ? wrow[n + 2] : 0.f;
                v.w = (n + 3 < Ncol) ? wrow[n + 3] : 0.f;
            }
            *reinterpret_cast<float4*>(&Bs[kk][nq * 4]) = v;
        }
        __syncthreads();
#pragma unroll
        for (int kk = 0; kk < BK; kk++) {
            // a: 8 rows = 4 packed pairs, loaded directly as 64-bit pairs (32B-aligned)
            ulonglong2 a01 = *reinterpret_cast<const ulonglong2*>(&As[kk][ty * 8]);
            ulonglong2 a23 = *reinterpret_cast<const ulonglong2*>(&As[kk][ty * 8 + 4]);
            unsigned long long a2[4] = {a01.x, a01.y, a23.x, a23.y};
            // b: 4 cols, each broadcast into both lanes (ALU-pipe movs, overlap FMA pipe)
            float4 bb = *reinterpret_cast<const float4*>(&Bs[kk][tx * 4]);
            unsigned long long b2[4];
            b2[0] = bcast_f32x2(bb.x);
            b2[1] = bcast_f32x2(bb.y);
            b2[2] = bcast_f32x2(bb.z);
            b2[3] = bcast_f32x2(bb.w);
#pragma unroll
            for (int i2 = 0; i2 < 4; i2++)
#pragma unroll
                for (int j = 0; j < 4; j++)
                    fma_f32x2(acc2[i2][j], a2[i2], b2[j]);
        }
        __syncthreads();
    }

#pragma unroll
    for (int i2 = 0; i2 < 4; i2++) {
#pragma unroll
        for (int j = 0; j < 4; j++) {
            int col = bn0 + tx * 4 + j;
            if (col >= Ncol) continue;
            float2 pr = *reinterpret_cast<const float2*>(&acc2[i2][j]);
#pragma unroll
            for (int half = 0; half < 2; half++) {
                int row = bm0 + ty * 8 + i2 * 2 + half;
                float v = half ? pr.y : pr.x;
                if (MODE == 0) {
                    v = fmaxf(v + bias[col], 0.f);
                } else if (MODE == 2) {
                    int b = row >> 10;            // row = b*P + p, P = 1024
                    int p = row & 1023;
                    int p0 = pairs[(b * P + p) * 2 + 0];
                    int p1 = pairs[(b * P + p) * 2 + 1];
                    v += gA[(size_t)(b * NE + p0) * HID + col] +
                         gB[(size_t)(b * NE + p1) * HID + col] + bias[col];
                    v = fmaxf(v, 0.f);
                }
                C[(size_t)row * Ncol + col] = v;
            }
        }
    }
}

// ---------------- entity pooling over mentions (with zero row at id 0) ----------------
__global__ void k_ent(const float* __restrict__ h1, const float* __restrict__ h2,
                      const int* __restrict__ e2m, const float* __restrict__ e2mask,
                      float* __restrict__ ent) {
    using namespace cfg;
    int i = blockIdx.x, b = blockIdx.y;
    __shared__ int idxs[MM];
    __shared__ float mk[MM];
    int tid = threadIdx.x;
    if (tid < MM) {
        idxs[tid] = e2m[(b * NE + i) * MM + tid];
        mk[tid] = e2mask[(b * NE + i) * MM + tid];
    }
    __syncthreads();
    float den = 1e-7f;
#pragma unroll
    for (int j = 0; j < MM; j++) den += mk[j];
    for (int c = tid; c < EE; c += blockDim.x) {
        float acc = 0.f;
#pragma unroll
        for (int j = 0; j < MM; j++) {
            int id = idxs[j];
            if (id > 0) {
                float v = (c < D) ? h1[(size_t)(b * N + id - 1) * D + c]
                                  : h2[(size_t)(b * N + id - 1) * D + (c - D)];
                acc = fmaf(v, mk[j], acc);
            }
        }
        ent[(size_t)(b * NE + i) * EE + c] = acc / den;
    }
}

// ---------------- per-pair nonlinear features [|hf-tf|, hf*tf] ----------------
__global__ void k_nl(const float* __restrict__ ent, const int* __restrict__ pairs,
                     float* __restrict__ nl) {
    using namespace cfg;
    int p = blockIdx.x, b = blockIdx.y;
    int p0 = pairs[(b * P + p) * 2 + 0];
    int p1 = pairs[(b * P + p) * 2 + 1];
    const float* hf = ent + (size_t)(b * NE + p0) * EE;
    const float* tf = ent + (size_t)(b * NE + p1) * EE;
    float* dst = nl + ((size_t)b * P + p) * HID;
    for (int c = threadIdx.x; c < EE; c += blockDim.x) {
        float a = hf[c], t = tf[c];
        dst[c] = fabsf(a - t);
        dst[EE + c] = a * t;
    }
}

// ---------------- final GEMM: hidden(4096x3200) @ W2(3200x97) + b2 ----------------
__global__ void __launch_bounds__(128)
k_out(const float* __restrict__ hid, const float* __restrict__ W2,
      const float* __restrict__ b2, float* __restrict__ out) {
    using namespace cfg;
    constexpr int RPB = 8, KC = 320;
    __shared__ float sh[RPB][KC];
    int row0 = blockIdx.x * RPB;
    int tid = threadIdx.x;
    float acc[RPB] = {};
    for (int k0 = 0; k0 < HID; k0 += KC) {
        for (int f = tid; f < RPB * KC; f += 128) {
            int r = f / KC, k = f % KC;
            sh[r][k] = hid[(size_t)(row0 + r) * HID + k0 + k];
        }
        __syncthreads();
        if (tid < OUT) {
            for (int kk = 0; kk < KC; kk++) {
                float w = W2[(size_t)(k0 + kk) * OUT + tid];
#pragma unroll
                for (int r = 0; r < RPB; r++) acc[r] = fmaf(sh[r][kk], w, acc[r]);
            }
        }
        __syncthreads();
    }
    if (tid < OUT) {
        float bb = b2[tid];
#pragma unroll
        for (int r = 0; r < RPB; r++)
            out[(size_t)(row0 + r) * OUT + tid] = acc[r] + bb;
    }
}

// ---------------- launch ----------------
extern "C" void kernel_launch(void* const* d_in, const int* in_sizes, int n_in,
                              void* d_out, int out_size) {
    using namespace cfg;
    const float* token     = (const float*)d_in[0];
    const float* cls       = (const float*)d_in[1];
    const int*   span_pos  = (const int*)d_in[2];
    const float* span_mask = (const float*)d_in[3];
    const int*   node_ner  = (const int*)d_in[4];
    const float* node_mask = (const float*)d_in[5];
    const int*   e2m       = (const int*)d_in[6];
    const float* e2m_mask  = (const float*)d_in[7];
    const int*   ent_pair  = (const int*)d_in[8];
    const int*   edge_src  = (const int*)d_in[9];
    const int*   edge_dst  = (const int*)d_in[10];
    const int*   edge_rel  = (const int*)d_in[11];
    const int*   ment_num  = (const int*)d_in[12];
    const float* nerEmb    = (const float*)d_in[13];
    const float* doc_W     = (const float*)d_in[14];
    const float* doc_b     = (const float*)d_in[15];
    const float* W_rel     = (const float*)d_in[16];
    const float* W_self    = (const float*)d_in[17];
    const float* gnn_b     = (const float*)d_in[18];
    const float* W1        = (const float*)d_in[19];
    const float* b1        = (const float*)d_in[20];
    const float* W2        = (const float*)d_in[21];
    const float* b2        = (const float*)d_in[22];
    float* out = (float*)d_out;
    (void)in_sizes; (void)n_in; (void)out_size;

    float *pdoc, *ph0, *ph1, *ph2, *pA, *pent, *pentA, *pentB, *pnl, *phid;
    cudaGetSymbolAddress((void**)&pdoc,  g_docproj);
    cudaGetSymbolAddress((void**)&ph0,   g_h0);
    cudaGetSymbolAddress((void**)&ph1,   g_h1);
    cudaGetSymbolAddress((void**)&ph2,   g_h2);
    cudaGetSymbolAddress((void**)&pA,    g_A);
    cudaGetSymbolAddress((void**)&pent,  g_ent);
    cudaGetSymbolAddress((void**)&pentA, g_entA);
    cudaGetSymbolAddress((void**)&pentB, g_entB);
    cudaGetSymbolAddress((void**)&pnl,   g_nl);
    cudaGetSymbolAddress((void**)&phid,  g_hidden);

    // 1) doc projection + node features
    k_docproj<<<dim3((D + 255) / 256, B), 256>>>(cls, doc_W, doc_b, pdoc);
    k_node<<<dim3(N, B), 256>>>(token, cls, span_pos, span_mask, node_ner, node_mask,
                                ment_num, nerEmb, pdoc, ph0);

    const size_t Atotal = (size_t)B * N * 16 * D;   // 13,107,200, %256 == 0
    const int initBlocks = (int)(Atotal / 256);

    // 2) GNN layer 0
    k_initA<<<initBlocks, 256>>>(ph0, pA);
    k_scatter<<<dim3(E, B), 256>>>(ph0, edge_src, edge_dst, edge_rel, pA);
    k_gemm<0><<<dim3((D + 63) / 64, (B * N) / 128), 256>>>(
        pA, KG, D, KSPLIT, W_rel, W_self, gnn_b, ph1, nullptr, nullptr, nullptr);

    // 3) GNN layer 1
    k_initA<<<initBlocks, 256>>>(ph1, pA);
    k_scatter<<<dim3(E, B), 256>>>(ph1, edge_src, edge_dst, edge_rel, pA);
    k_gemm<0><<<dim3((D + 63) / 64, (B * N) / 128), 256>>>(
        pA, KG, D, KSPLIT, W_rel + (size_t)R * D * D, W_self + (size_t)D * D,
        gnn_b + D, ph2, nullptr, nullptr, nullptr);

    // 4) entity pooling
    k_ent<<<dim3(NE, B), 256>>>(ph1, ph2, e2m, e2m_mask, pent);

    // 5) linear halves of pair MLP: entA = ent@W1[0:EE], entB = ent@W1[EE:2EE]
    k_gemm<1><<<dim3(HID / 64, (B * NE) / 128), 256>>>(
        pent, EE, HID, EE, W1, W1, nullptr, pentA, nullptr, nullptr, nullptr);
    k_gemm<1><<<dim3(HID / 64, (B * NE) / 128), 256>>>(
        pent, EE, HID, EE, W1 + (size_t)EE * HID, W1, nullptr, pentB,
        nullptr, nullptr, nullptr);

    // 6) nonlinear pair features + big GEMM with fused gather epilogue
    k_nl<<<dim3(P, B), 256>>>(pent, ent_pair, pnl);
    k_gemm<2><<<dim3(HID / 64, (B * P) / 128), 256>>>(
        pnl, HID, HID, HID, W1 + (size_t)2 * EE * HID, W1, b1, phid,
        pentA, pentB, ent_pair);

    // 7) output layer
    k_out<<<(B * P) / 8, 128>>>(phid, W2, b2, out);
}

// round 4
// speedup vs baseline: 1.5280x; 1.4823x over previous
#include <cuda_runtime.h>
#include <cuda_bf16.h>
#include <cstdint>
#include <cstddef>

namespace cfg {
constexpr int B = 4;
constexpr int T = 512;
constexpr int H = 768;
constexpr int N = 256;
constexpr int S = 16;
constexpr int NERD = 32;
constexpr int D = 800;          // H + NERD
constexpr int R = 15;
constexpr int NE = 64;
constexpr int MM = 8;
constexpr int P = 1024;
constexpr int E = 4096;
constexpr int OUT = 97;
constexpr int EE = 1600;        // 2*D
constexpr int HID = 3200;       // 2*EE
constexpr int KG = 12800;       // 16*D  ([S_0..S_14 | h])
constexpr int KSPLIT = 12000;   // R*D
}

// ---------------- scratch (device globals; no runtime allocation) ----------------
__device__ float g_docproj[cfg::B * cfg::D];
__device__ float g_h0[cfg::B * cfg::N * cfg::D];
__device__ float g_h1[cfg::B * cfg::N * cfg::D];
__device__ float g_h2[cfg::B * cfg::N * cfg::D];
__device__ float g_A[(size_t)cfg::B * cfg::N * 16 * cfg::D];          // 52 MB
__device__ float g_ent[cfg::B * cfg::NE * cfg::EE];
__device__ float g_entA[cfg::B * cfg::NE * cfg::HID];
__device__ float g_entB[cfg::B * cfg::NE * cfg::HID];
__device__ float g_nl[(size_t)cfg::B * cfg::P * cfg::HID];            // 52 MB
__device__ float g_hidden[(size_t)cfg::B * cfg::P * cfg::HID];        // 52 MB

// ================= helpers =================
__device__ __forceinline__ uint32_t smem_u32(const void* p) {
    uint32_t a;
    asm("{ .reg .u64 t; cvta.to.shared.u64 t, %1; cvt.u32.u64 %0, t; }"
        : "=r"(a) : "l"(p));
    return a;
}
__device__ __forceinline__ void ldsm4(uint32_t* r, uint32_t addr) {
    asm volatile("ldmatrix.sync.aligned.m8n8.x4.shared.b16 {%0,%1,%2,%3}, [%4];"
                 : "=r"(r[0]), "=r"(r[1]), "=r"(r[2]), "=r"(r[3]) : "r"(addr));
}
__device__ __forceinline__ void mma_bf16(float* c, const uint32_t* a,
                                         uint32_t b0, uint32_t b1) {
    asm volatile(
        "mma.sync.aligned.m16n8k16.row.col.f32.bf16.bf16.f32 "
        "{%0,%1,%2,%3}, {%4,%5,%6,%7}, {%8,%9}, {%0,%1,%2,%3};"
        : "+f"(c[0]), "+f"(c[1]), "+f"(c[2]), "+f"(c[3])
        : "r"(a[0]), "r"(a[1]), "r"(a[2]), "r"(a[3]), "r"(b0), "r"(b1));
}
__device__ __forceinline__ void split_bf16(float x, __nv_bfloat16& h, __nv_bfloat16& l) {
    h = __float2bfloat16_rn(x);
    l = __float2bfloat16_rn(x - __bfloat162float(h));
}
__device__ __forceinline__ uint32_t pkbf(__nv_bfloat16 a, __nv_bfloat16 b) {
    __nv_bfloat162 t = __halves2bfloat162(a, b);
    return *reinterpret_cast<uint32_t*>(&t);
}

// =====================================================================
// Split-bf16 HMMA GEMM: C[M,Ncol] = epilogue(A[M,K] @ W[K,Ncol])
//   W row k from W0 (k < Ksplit) else Wsf (k - Ksplit).
// MODE 0: relu(acc + bias[col])
// MODE 1: acc
// MODE 2: relu(acc + gA[p0,col] + gB[p1,col] + bias[col])   (pair gather)
// MODE 3: acc + bias[col]
// =====================================================================
template <int BM, int BN, int MODE>
__global__ void __launch_bounds__(256)
k_tgemm(const float* __restrict__ A, int K, int Ncol, int Ksplit,
        const float* __restrict__ W0, const float* __restrict__ Wsf,
        const float* __restrict__ bias, float* __restrict__ C,
        const float* __restrict__ gA, const float* __restrict__ gB,
        const int* __restrict__ pairs) {
    using namespace cfg;
    constexpr int BK = 32;
    constexpr int WNG = (BN == 128) ? 4 : 2;
    constexpr int WMG = 8 / WNG;
    constexpr int WTM = BM / WMG;        // 64 or 32
    constexpr int WTN = BN / WNG;        // 32
    constexpr int MATOMS = WTM / 16;     // 4 or 2
    constexpr int NAT16 = WTN / 16;      // 2
    constexpr int NATOMS = WTN / 8;      // 4
    constexpr int STRIDE = 40;           // bf16 per smem row (80 B)

    __shared__ __align__(16) __nv_bfloat16 sAhi[BM * STRIDE];
    __shared__ __align__(16) __nv_bfloat16 sAlo[BM * STRIDE];
    __shared__ __align__(16) __nv_bfloat16 sBhi[BN * STRIDE];
    __shared__ __align__(16) __nv_bfloat16 sBlo[BN * STRIDE];

    const int tid = threadIdx.x;
    const int wid = tid >> 5, lane = tid & 31;
    const int wn = wid % WNG, wm = wid / WNG;
    const int bm0 = blockIdx.y * BM, bn0 = blockIdx.x * BN;

    const uint32_t uAhi = smem_u32(sAhi), uAlo = smem_u32(sAlo);
    const uint32_t uBhi = smem_u32(sBhi), uBlo = smem_u32(sBlo);

    float acc[MATOMS][NATOMS][4];
#pragma unroll
    for (int i = 0; i < MATOMS; i++)
#pragma unroll
        for (int j = 0; j < NATOMS; j++)
#pragma unroll
            for (int q = 0; q < 4; q++) acc[i][j][q] = 0.f;

    const float* Abase = A + (size_t)bm0 * K;
    const int lrow = lane & 15;
    const int lhalf = lane >> 4;

    for (int k0 = 0; k0 < K; k0 += BK) {
        // ---- A stage: BM x 32 f32 -> hi/lo bf16 smem [m][k] ----
#pragma unroll
        for (int i = 0; i < BM * 8 / 256; i++) {
            int f = tid + i * 256;
            int kq = f & 7;
            int row = f >> 3;
            float4 v = *reinterpret_cast<const float4*>(
                Abase + (size_t)row * K + k0 + kq * 4);
            __nv_bfloat16 hx, lx, hy, ly, hz, lz, hw, lw;
            split_bf16(v.x, hx, lx); split_bf16(v.y, hy, ly);
            split_bf16(v.z, hz, lz); split_bf16(v.w, hw, lw);
            uint32_t off = (uint32_t)(row * 80 + kq * 8);
            *reinterpret_cast<uint2*>((char*)sAhi + off) =
                make_uint2(pkbf(hx, hy), pkbf(hz, hw));
            *reinterpret_cast<uint2*>((char*)sAlo + off) =
                make_uint2(pkbf(lx, ly), pkbf(lz, lw));
        }
        // ---- B stage: W[k0..k0+31][bn0..bn0+BN) -> smem [n][k] hi/lo ----
        constexpr int NV4 = BN / 4;
#pragma unroll
        for (int i = 0; i < (16 * NV4) / 256; i++) {
            int f = tid + i * 256;
            int n4 = f % NV4;
            int k2 = f / NV4;            // k-pair 0..15
            int kg0 = k0 + 2 * k2;
            int kg1 = kg0 + 1;
            const float* r0 = (kg0 < Ksplit) ? W0 + (size_t)kg0 * Ncol
                                             : Wsf + (size_t)(kg0 - Ksplit) * Ncol;
            const float* r1 = (kg1 < Ksplit) ? W0 + (size_t)kg1 * Ncol
                                             : Wsf + (size_t)(kg1 - Ksplit) * Ncol;
            int n = bn0 + n4 * 4;
            float x0[4], x1[4];
            if (((Ncol & 3) == 0) && (n + 3 < Ncol)) {
                float4 a0 = *reinterpret_cast<const float4*>(r0 + n);
                float4 a1 = *reinterpret_cast<const float4*>(r1 + n);
                x0[0] = a0.x; x0[1] = a0.y; x0[2] = a0.z; x0[3] = a0.w;
                x1[0] = a1.x; x1[1] = a1.y; x1[2] = a1.z; x1[3] = a1.w;
            } else {
#pragma unroll
                for (int j = 0; j < 4; j++) {
                    x0[j] = (n + j < Ncol) ? r0[n + j] : 0.f;
                    x1[j] = (n + j < Ncol) ? r1[n + j] : 0.f;
                }
            }
#pragma unroll
            for (int j = 0; j < 4; j++) {
                int rowl = n4 * 4 + j;
                __nv_bfloat16 h0, l0, h1, l1;
                split_bf16(x0[j], h0, l0);
                split_bf16(x1[j], h1, l1);
                uint32_t off = (uint32_t)(rowl * 80 +
                    ((((k2 >> 2) ^ ((rowl >> 2) & 3)) << 4) | ((k2 & 3) << 2)));
                *reinterpret_cast<uint32_t*>((char*)sBhi + off) = pkbf(h0, h1);
                *reinterpret_cast<uint32_t*>((char*)sBlo + off) = pkbf(l0, l1);
            }
        }
        __syncthreads();

        // ---- compute: 2 k16 steps x (hh + hl + lh) ----
#pragma unroll
        for (int s = 0; s < 2; s++) {
            uint32_t ah[MATOMS][4], al[MATOMS][4];
#pragma unroll
            for (int ma = 0; ma < MATOMS; ma++) {
                int row = wm * WTM + ma * 16 + lrow;
                uint32_t off = (uint32_t)(row * 80 + (s * 2 + lhalf) * 16);
                ldsm4(ah[ma], uAhi + off);
                ldsm4(al[ma], uAlo + off);
            }
            uint32_t bh[NAT16][4], bl[NAT16][4];
#pragma unroll
            for (int ng = 0; ng < NAT16; ng++) {
                int rb = wn * WTN + ng * 16 + lrow;
                int c = s * 2 + lhalf;
                uint32_t off = (uint32_t)(rb * 80 + ((c ^ ((rb >> 2) & 3)) << 4));
                ldsm4(bh[ng], uBhi + off);
                ldsm4(bl[ng], uBlo + off);
            }
#pragma unroll
            for (int ma = 0; ma < MATOMS; ma++)
#pragma unroll
                for (int na = 0; na < NATOMS; na++)
                    mma_bf16(acc[ma][na], ah[ma], bh[na >> 1][na & 1],
                             bh[na >> 1][2 + (na & 1)]);
#pragma unroll
            for (int ma = 0; ma < MATOMS; ma++)
#pragma unroll
                for (int na = 0; na < NATOMS; na++)
                    mma_bf16(acc[ma][na], ah[ma], bl[na >> 1][na & 1],
                             bl[na >> 1][2 + (na & 1)]);
#pragma unroll
            for (int ma = 0; ma < MATOMS; ma++)
#pragma unroll
                for (int na = 0; na < NATOMS; na++)
                    mma_bf16(acc[ma][na], al[ma], bh[na >> 1][na & 1],
                             bh[na >> 1][2 + (na & 1)]);
        }
        __syncthreads();
    }

    // ---- epilogue ----
    const int gid = lane >> 2, tig = lane & 3;
#pragma unroll
    for (int ma = 0; ma < MATOMS; ma++) {
        int row0 = bm0 + wm * WTM + ma * 16;
#pragma unroll
        for (int na = 0; na < NATOMS; na++) {
            int col0 = bn0 + wn * WTN + na * 8 + 2 * tig;
#pragma unroll
            for (int half = 0; half < 2; half++) {
                int row = row0 + gid + half * 8;
                float v0 = acc[ma][na][half * 2 + 0];
                float v1 = acc[ma][na][half * 2 + 1];
                if (MODE == 0) {
                    if (col0 < Ncol)
                        C[(size_t)row * Ncol + col0] = fmaxf(v0 + bias[col0], 0.f);
                    if (col0 + 1 < Ncol)
                        C[(size_t)row * Ncol + col0 + 1] = fmaxf(v1 + bias[col0 + 1], 0.f);
                } else if (MODE == 1) {
                    if (col0 < Ncol) C[(size_t)row * Ncol + col0] = v0;
                    if (col0 + 1 < Ncol) C[(size_t)row * Ncol + col0 + 1] = v1;
                } else if (MODE == 2) {
                    int b = row >> 10;          // row = b*P + p, P = 1024
                    int pp = row & 1023;
                    int p0 = pairs[(b * P + pp) * 2 + 0];
                    int p1 = pairs[(b * P + pp) * 2 + 1];
                    const float* ga = gA + (size_t)(b * NE + p0) * HID;
                    const float* gb = gB + (size_t)(b * NE + p1) * HID;
                    C[(size_t)row * Ncol + col0] =
                        fmaxf(v0 + ga[col0] + gb[col0] + bias[col0], 0.f);
                    C[(size_t)row * Ncol + col0 + 1] =
                        fmaxf(v1 + ga[col0 + 1] + gb[col0 + 1] + bias[col0 + 1], 0.f);
                } else {  // MODE 3
                    if (col0 < Ncol)
                        C[(size_t)row * Ncol + col0] = v0 + bias[col0];
                    if (col0 + 1 < Ncol)
                        C[(size_t)row * Ncol + col0 + 1] = v1 + bias[col0 + 1];
                }
            }
        }
    }
}

// ---------------- doc projection: relu(cls @ doc_W + doc_b) ----------------
__global__ void k_docproj(const float* __restrict__ cls, const float* __restrict__ W,
                          const float* __restrict__ bvec, float* __restrict__ out) {
    using namespace cfg;
    int b = blockIdx.y;
    int d = blockIdx.x * blockDim.x + threadIdx.x;
    if (d >= D) return;
    float acc = bvec[d];
    const float* c = cls + b * H;
    for (int h = 0; h < H; h++) acc = fmaf(c[h], W[(size_t)h * D + d], acc);
    out[b * D + d] = fmaxf(acc, 0.f);
}

// ---------------- node features h0 ----------------
__global__ void k_node(const float* __restrict__ token, const float* __restrict__ cls,
                       const int* __restrict__ pos, const float* __restrict__ smask,
                       const int* __restrict__ ner, const float* __restrict__ nmask,
                       const int* __restrict__ ment, const float* __restrict__ nerEmb,
                       const float* __restrict__ docproj, float* __restrict__ h0) {
    using namespace cfg;
    const int n = blockIdx.x, b = blockIdx.y;
    __shared__ int sp[S];
    __shared__ float sm[S];
    int tid = threadIdx.x;
    if (tid < S) {
        sp[tid] = pos[(b * N + n) * S + tid];
        sm[tid] = smask[(b * N + n) * S + tid];
    }
    __syncthreads();
    float* dst = h0 + (size_t)(b * N + n) * D;
    if (n == ment[b]) {
        for (int d = tid; d < D; d += blockDim.x) dst[d] = docproj[b * D + d];
        return;
    }
    float den = 0.1f;
#pragma unroll
    for (int s = 0; s < S; s++) den += sm[s];
    float nm = nmask[b * N + n];
    int nerIdx = ner[b * N + n];
    for (int d = tid; d < D; d += blockDim.x) {
        float v;
        if (d < H) {
            float acc = 0.f;
#pragma unroll
            for (int s = 0; s < S; s++)
                acc = fmaf(token[((size_t)b * T + sp[s]) * H + d], sm[s], acc);
            v = acc / den + cls[b * H + d];
        } else {
            v = nerEmb[nerIdx * NERD + (d - H)];
        }
        dst[d] = v * nm;
    }
}

// ---------------- init A buffer: slots 0..14 = 0, slot 15 = h ----------------
__global__ void k_initA(const float* __restrict__ hin, float* __restrict__ A) {
    using namespace cfg;
    size_t idx = (size_t)blockIdx.x * blockDim.x + threadIdx.x;
    int d = (int)(idx % D);
    size_t rest = idx / D;
    int r = (int)(rest & 15);
    size_t bn = rest >> 4;
    A[idx] = (r == 15) ? hin[bn * D + d] : 0.f;
}

// ---------------- edge scatter: A[b,dst,rel,:] += h[b,src,:] ----------------
__global__ void k_scatter(const float* __restrict__ hin, const int* __restrict__ src,
                          const int* __restrict__ dst, const int* __restrict__ rel,
                          float* __restrict__ A) {
    using namespace cfg;
    int e = blockIdx.x, b = blockIdx.y;
    int sIdx = src[b * E + e];
    int dIdx = dst[b * E + e];
    int r = rel[b * E + e];
    const float* hrow = hin + (size_t)(b * N + sIdx) * D;
    float* arow = A + ((size_t)(b * N + dIdx) * 16 + r) * D;
    for (int d = threadIdx.x; d < D; d += blockDim.x)
        atomicAdd(&arow[d], hrow[d]);
}

// ---------------- entity pooling over mentions ----------------
__global__ void k_ent(const float* __restrict__ h1, const float* __restrict__ h2,
                      const int* __restrict__ e2m, const float* __restrict__ e2mask,
                      float* __restrict__ ent) {
    using namespace cfg;
    int i = blockIdx.x, b = blockIdx.y;
    __shared__ int idxs[MM];
    __shared__ float mk[MM];
    int tid = threadIdx.x;
    if (tid < MM) {
        idxs[tid] = e2m[(b * NE + i) * MM + tid];
        mk[tid] = e2mask[(b * NE + i) * MM + tid];
    }
    __syncthreads();
    float den = 1e-7f;
#pragma unroll
    for (int j = 0; j < MM; j++) den += mk[j];
    for (int c = tid; c < EE; c += blockDim.x) {
        float acc = 0.f;
#pragma unroll
        for (int j = 0; j < MM; j++) {
            int id = idxs[j];
            if (id > 0) {
                float v = (c < D) ? h1[(size_t)(b * N + id - 1) * D + c]
                                  : h2[(size_t)(b * N + id - 1) * D + (c - D)];
                acc = fmaf(v, mk[j], acc);
            }
        }
        ent[(size_t)(b * NE + i) * EE + c] = acc / den;
    }
}

// ---------------- per-pair nonlinear features [|hf-tf|, hf*tf] ----------------
__global__ void k_nl(const float* __restrict__ ent, const int* __restrict__ pairs,
                     float* __restrict__ nl) {
    using namespace cfg;
    int p = blockIdx.x, b = blockIdx.y;
    int p0 = pairs[(b * P + p) * 2 + 0];
    int p1 = pairs[(b * P + p) * 2 + 1];
    const float* hf = ent + (size_t)(b * NE + p0) * EE;
    const float* tf = ent + (size_t)(b * NE + p1) * EE;
    float* dst = nl + ((size_t)b * P + p) * HID;
    for (int c = threadIdx.x; c < EE; c += blockDim.x) {
        float a = hf[c], t = tf[c];
        dst[c] = fabsf(a - t);
        dst[EE + c] = a * t;
    }
}

// ---------------- launch ----------------
extern "C" void kernel_launch(void* const* d_in, const int* in_sizes, int n_in,
                              void* d_out, int out_size) {
    using namespace cfg;
    const float* token     = (const float*)d_in[0];
    const float* cls       = (const float*)d_in[1];
    const int*   span_pos  = (const int*)d_in[2];
    const float* span_mask = (const float*)d_in[3];
    const int*   node_ner  = (const int*)d_in[4];
    const float* node_mask = (const float*)d_in[5];
    const int*   e2m       = (const int*)d_in[6];
    const float* e2m_mask  = (const float*)d_in[7];
    const int*   ent_pair  = (const int*)d_in[8];
    const int*   edge_src  = (const int*)d_in[9];
    const int*   edge_dst  = (const int*)d_in[10];
    const int*   edge_rel  = (const int*)d_in[11];
    const int*   ment_num  = (const int*)d_in[12];
    const float* nerEmb    = (const float*)d_in[13];
    const float* doc_W     = (const float*)d_in[14];
    const float* doc_b     = (const float*)d_in[15];
    const float* W_rel     = (const float*)d_in[16];
    const float* W_self    = (const float*)d_in[17];
    const float* gnn_b     = (const float*)d_in[18];
    const float* W1        = (const float*)d_in[19];
    const float* b1        = (const float*)d_in[20];
    const float* W2        = (const float*)d_in[21];
    const float* b2        = (const float*)d_in[22];
    float* out = (float*)d_out;
    (void)in_sizes; (void)n_in; (void)out_size;

    float *pdoc, *ph0, *ph1, *ph2, *pA, *pent, *pentA, *pentB, *pnl, *phid;
    cudaGetSymbolAddress((void**)&pdoc,  g_docproj);
    cudaGetSymbolAddress((void**)&ph0,   g_h0);
    cudaGetSymbolAddress((void**)&ph1,   g_h1);
    cudaGetSymbolAddress((void**)&ph2,   g_h2);
    cudaGetSymbolAddress((void**)&pA,    g_A);
    cudaGetSymbolAddress((void**)&pent,  g_ent);
    cudaGetSymbolAddress((void**)&pentA, g_entA);
    cudaGetSymbolAddress((void**)&pentB, g_entB);
    cudaGetSymbolAddress((void**)&pnl,   g_nl);
    cudaGetSymbolAddress((void**)&phid,  g_hidden);

    // 1) doc projection + node features
    k_docproj<<<dim3((D + 255) / 256, B), 256>>>(cls, doc_W, doc_b, pdoc);
    k_node<<<dim3(N, B), 256>>>(token, cls, span_pos, span_mask, node_ner, node_mask,
                                ment_num, nerEmb, pdoc, ph0);

    const size_t Atotal = (size_t)B * N * 16 * D;
    const int initBlocks = (int)(Atotal / 256);

    // 2) GNN layer 0
    k_initA<<<initBlocks, 256>>>(ph0, pA);
    k_scatter<<<dim3(E, B), 256>>>(ph0, edge_src, edge_dst, edge_rel, pA);
    k_tgemm<128, 64, 0><<<dim3((D + 63) / 64, (B * N) / 128), 256>>>(
        pA, KG, D, KSPLIT, W_rel, W_self, gnn_b, ph1, nullptr, nullptr, nullptr);

    // 3) GNN layer 1
    k_initA<<<initBlocks, 256>>>(ph1, pA);
    k_scatter<<<dim3(E, B), 256>>>(ph1, edge_src, edge_dst, edge_rel, pA);
    k_tgemm<128, 64, 0><<<dim3((D + 63) / 64, (B * N) / 128), 256>>>(
        pA, KG, D, KSPLIT, W_rel + (size_t)R * D * D, W_self + (size_t)D * D,
        gnn_b + D, ph2, nullptr, nullptr, nullptr);

    // 4) entity pooling
    k_ent<<<dim3(NE, B), 256>>>(ph1, ph2, e2m, e2m_mask, pent);

    // 5) linear halves of pair MLP
    k_tgemm<128, 128, 1><<<dim3(HID / 128, (B * NE) / 128), 256>>>(
        pent, EE, HID, EE, W1, W1, nullptr, pentA, nullptr, nullptr, nullptr);
    k_tgemm<128, 128, 1><<<dim3(HID / 128, (B * NE) / 128), 256>>>(
        pent, EE, HID, EE, W1 + (size_t)EE * HID, W1, nullptr, pentB,
        nullptr, nullptr, nullptr);

    // 6) nonlinear pair features + big GEMM with fused gather epilogue
    k_nl<<<dim3(P, B), 256>>>(pent, ent_pair, pnl);
    k_tgemm<128, 128, 2><<<dim3(HID / 128, (B * P) / 128), 256>>>(
        pnl, HID, HID, HID, W1 + (size_t)2 * EE * HID, W1, b1, phid,
        pentA, pentB, ent_pair);

    // 7) output layer: hidden(4096x3200) @ W2(3200x97) + b2
    k_tgemm<128, 128, 3><<<dim3(1, (B * P) / 128), 256>>>(
        phid, HID, OUT, HID, W2, W2, b2, out, nullptr, nullptr, nullptr);
}

// round 5
// speedup vs baseline: 3.0410x; 1.9901x over previous
#include <cuda_runtime.h>
#include <cuda_bf16.h>
#include <cstdint>
#include <cstddef>

namespace cfg {
constexpr int B = 4;
constexpr int T = 512;
constexpr int H = 768;
constexpr int N = 256;
constexpr int S = 16;
constexpr int NERD = 32;
constexpr int D = 800;          // H + NERD
constexpr int R = 15;
constexpr int NE = 64;
constexpr int MM = 8;
constexpr int P = 1024;
constexpr int E = 4096;
constexpr int OUT = 97;
constexpr int EE = 1600;        // 2*D
constexpr int HID = 3200;       // 2*EE
constexpr int KG = 12800;       // 16*D  ([S_0..S_14 | h])
constexpr int KSPLIT = 12000;   // R*D
constexpr int NPG = 832;        // GNN N padded to 13*64
}

// ---------------- scratch (device globals; no runtime allocation) ----------------
__device__ float g_docproj[cfg::B * cfg::D];
__device__ float g_h0[cfg::B * cfg::N * cfg::D];
__device__ float g_h1[cfg::B * cfg::N * cfg::D];
__device__ float g_h2[cfg::B * cfg::N * cfg::D];
__device__ float g_A[(size_t)cfg::B * cfg::N * 16 * cfg::D];             // 52 MB f32
__device__ __nv_bfloat16 g_Ahi[(size_t)cfg::B * cfg::N * 16 * cfg::D];
__device__ __nv_bfloat16 g_Alo[(size_t)cfg::B * cfg::N * 16 * cfg::D];
__device__ __nv_bfloat16 g_WgT_hi[2][(size_t)cfg::NPG * cfg::KG];
__device__ __nv_bfloat16 g_WgT_lo[2][(size_t)cfg::NPG * cfg::KG];
__device__ __nv_bfloat16 g_enthi[cfg::B * cfg::NE * cfg::EE];
__device__ __nv_bfloat16 g_entlo[cfg::B * cfg::NE * cfg::EE];
__device__ __nv_bfloat16 g_W1linT_hi[(size_t)2 * cfg::HID * cfg::EE];    // [6400][1600]
__device__ __nv_bfloat16 g_W1linT_lo[(size_t)2 * cfg::HID * cfg::EE];
__device__ __nv_bfloat16 g_W1nlT_hi[(size_t)cfg::HID * cfg::HID];        // [3200][3200]
__device__ __nv_bfloat16 g_W1nlT_lo[(size_t)cfg::HID * cfg::HID];
__device__ __nv_bfloat16 g_W2T_hi[128 * cfg::HID];
__device__ __nv_bfloat16 g_W2T_lo[128 * cfg::HID];
__device__ float g_entAB[(size_t)cfg::B * cfg::NE * 2 * cfg::HID];       // [256][6400]
__device__ __nv_bfloat16 g_nlhi[(size_t)cfg::B * cfg::P * cfg::HID];
__device__ __nv_bfloat16 g_nllo[(size_t)cfg::B * cfg::P * cfg::HID];
__device__ __nv_bfloat16 g_hidhi[(size_t)cfg::B * cfg::P * cfg::HID];
__device__ __nv_bfloat16 g_hidlo[(size_t)cfg::B * cfg::P * cfg::HID];

// ================= helpers =================
__device__ __forceinline__ uint32_t smem_u32(const void* p) {
    uint32_t a;
    asm("{ .reg .u64 t; cvta.to.shared.u64 t, %1; cvt.u32.u64 %0, t; }"
        : "=r"(a) : "l"(p));
    return a;
}
__device__ __forceinline__ void ldsm4(uint32_t* r, uint32_t addr) {
    asm volatile("ldmatrix.sync.aligned.m8n8.x4.shared.b16 {%0,%1,%2,%3}, [%4];"
                 : "=r"(r[0]), "=r"(r[1]), "=r"(r[2]), "=r"(r[3]) : "r"(addr));
}
__device__ __forceinline__ void mma_bf16(float* c, const uint32_t* a,
                                         uint32_t b0, uint32_t b1) {
    asm volatile(
        "mma.sync.aligned.m16n8k16.row.col.f32.bf16.bf16.f32 "
        "{%0,%1,%2,%3}, {%4,%5,%6,%7}, {%8,%9}, {%0,%1,%2,%3};"
        : "+f"(c[0]), "+f"(c[1]), "+f"(c[2]), "+f"(c[3])
        : "r"(a[0]), "r"(a[1]), "r"(a[2]), "r"(a[3]), "r"(b0), "r"(b1));
}
__device__ __forceinline__ void split_bf16(float x, __nv_bfloat16& h, __nv_bfloat16& l) {
    h = __float2bfloat16_rn(x);
    l = __float2bfloat16_rn(x - __bfloat162float(h));
}
__device__ __forceinline__ uint32_t pkbf(__nv_bfloat16 a, __nv_bfloat16 b) {
    __nv_bfloat162 t = __halves2bfloat162(a, b);
    return *reinterpret_cast<uint32_t*>(&t);
}
__device__ __forceinline__ void cpa16(uint32_t dst, const void* src) {
    asm volatile("cp.async.cg.shared.global [%0], [%1], 16;" :: "r"(dst), "l"(src));
}
__device__ __forceinline__ void cpa_commit() {
    asm volatile("cp.async.commit_group;" ::: "memory");
}
template <int NN>
__device__ __forceinline__ void cpa_wait() {
    asm volatile("cp.async.wait_group %0;" :: "n"(NN) : "memory");
}

// =====================================================================
// Double-buffered split-bf16 HMMA GEMM on pre-converted operands.
//   A: hi/lo bf16 [M][K] row-major.   B: hi/lo bf16 [N][K] row-major (W^T).
// MODE 0: Cf = relu(acc + bias[col])
// MODE 1: Cf = acc
// MODE 2: v = relu(acc + gAB[p0,col] + gAB[p1,HID+col] + bias[col]) -> split to Chi/Clo
// MODE 3: Cf = acc + bias[col]
// =====================================================================
template <int BN, int MODE>
__global__ void __launch_bounds__(256)
k_mm(const __nv_bfloat16* __restrict__ Ahi, const __nv_bfloat16* __restrict__ Alo,
     const __nv_bfloat16* __restrict__ Bhi, const __nv_bfloat16* __restrict__ Blo,
     int K, int Ncol,
     const float* __restrict__ bias, float* __restrict__ Cf,
     __nv_bfloat16* __restrict__ Chi, __nv_bfloat16* __restrict__ Clo,
     const float* __restrict__ gAB, const int* __restrict__ pairs) {
    using namespace cfg;
    constexpr int BM = 128, BK = 64;
    constexpr int WNG = (BN == 128) ? 4 : 2;
    constexpr int WMG = 8 / WNG;
    constexpr int WTM = BM / WMG;        // 64 or 32
    constexpr int WTN = BN / WNG;        // 32
    constexpr int MATOMS = WTM / 16;
    constexpr int NAT16 = WTN / 16;      // 2
    constexpr int NATOMS = WTN / 8;      // 4
    constexpr int RB = BM * 128;         // bytes of one A half-tile
    constexpr int RBB = BN * 128;        // bytes of one B half-tile
    constexpr int SB = 2 * RB + 2 * RBB; // stage bytes

    extern __shared__ char smem[];
    const uint32_t sbase = smem_u32(smem);
    const int tid = threadIdx.x;
    const int wid = tid >> 5, lane = tid & 31;
    const int wn = wid % WNG, wm = wid / WNG;
    const int bm0 = blockIdx.y * BM, bn0 = blockIdx.x * BN;
    const int lrow = lane & 15, lhalf = lane >> 4;

    float acc[MATOMS][NATOMS][4];
#pragma unroll
    for (int i = 0; i < MATOMS; i++)
#pragma unroll
        for (int j = 0; j < NATOMS; j++)
#pragma unroll
            for (int q = 0; q < 4; q++) acc[i][j][q] = 0.f;

    const __nv_bfloat16* Ah = Ahi + (size_t)bm0 * K;
    const __nv_bfloat16* Al = Alo + (size_t)bm0 * K;
    const __nv_bfloat16* Bh = Bhi + (size_t)bn0 * K;
    const __nv_bfloat16* Bl = Blo + (size_t)bn0 * K;

    auto load_stage = [&](int s, int k0) {
        uint32_t base = sbase + s * SB;
#pragma unroll
        for (int i = 0; i < BM * 8 / 256; i++) {
            int f = tid + i * 256;
            int row = f >> 3, g = f & 7;
            uint32_t d = base + row * 128 + ((g ^ (row & 7)) << 4);
            size_t so = (size_t)row * K + k0 + g * 8;
            cpa16(d, Ah + so);
            cpa16(d + RB, Al + so);
        }
#pragma unroll
        for (int i = 0; i < BN * 8 / 256; i++) {
            int f = tid + i * 256;
            int row = f >> 3, g = f & 7;
            uint32_t d = base + 2 * RB + row * 128 + ((g ^ (row & 7)) << 4);
            size_t so = (size_t)row * K + k0 + g * 8;
            cpa16(d, Bh + so);
            cpa16(d + RBB, Bl + so);
        }
    };

    const int nch = K / BK;
    load_stage(0, 0);
    cpa_commit();

    for (int ch = 0; ch < nch; ch++) {
        if (ch + 1 < nch) {
            load_stage((ch + 1) & 1, (ch + 1) * BK);
            cpa_commit();
            cpa_wait<1>();
        } else {
            cpa_wait<0>();
        }
        __syncthreads();

        uint32_t sA = sbase + (ch & 1) * SB;
        uint32_t sB = sA + 2 * RB;
#pragma unroll
        for (int s = 0; s < 4; s++) {
            uint32_t ah[MATOMS][4], al[MATOMS][4];
#pragma unroll
            for (int ma = 0; ma < MATOMS; ma++) {
                int row = wm * WTM + ma * 16 + lrow;
                uint32_t off = sA + row * 128 + (((s * 2 + lhalf) ^ (row & 7)) << 4);
                ldsm4(ah[ma], off);
                ldsm4(al[ma], off + RB);
            }
            uint32_t bh[NAT16][4], bl[NAT16][4];
#pragma unroll
            for (int ng = 0; ng < NAT16; ng++) {
                int rb = wn * WTN + ng * 16 + lrow;
                uint32_t off = sB + rb * 128 + (((s * 2 + lhalf) ^ (rb & 7)) << 4);
                ldsm4(bh[ng], off);
                ldsm4(bl[ng], off + RBB);
            }
#pragma unroll
            for (int ma = 0; ma < MATOMS; ma++)
#pragma unroll
                for (int na = 0; na < NATOMS; na++)
                    mma_bf16(acc[ma][na], ah[ma], bh[na >> 1][na & 1],
                             bh[na >> 1][2 + (na & 1)]);
#pragma unroll
            for (int ma = 0; ma < MATOMS; ma++)
#pragma unroll
                for (int na = 0; na < NATOMS; na++)
                    mma_bf16(acc[ma][na], ah[ma], bl[na >> 1][na & 1],
                             bl[na >> 1][2 + (na & 1)]);
#pragma unroll
            for (int ma = 0; ma < MATOMS; ma++)
#pragma unroll
                for (int na = 0; na < NATOMS; na++)
                    mma_bf16(acc[ma][na], al[ma], bh[na >> 1][na & 1],
                             bh[na >> 1][2 + (na & 1)]);
        }
        __syncthreads();
    }

    // ---- epilogue ----
    const int gid = lane >> 2, tig = lane & 3;
#pragma unroll
    for (int ma = 0; ma < MATOMS; ma++) {
        int rowbase = bm0 + wm * WTM + ma * 16;
#pragma unroll
        for (int na = 0; na < NATOMS; na++) {
            int col0 = bn0 + wn * WTN + na * 8 + 2 * tig;
#pragma unroll
            for (int half = 0; half < 2; half++) {
                int row = rowbase + gid + half * 8;
                float v0 = acc[ma][na][half * 2 + 0];
                float v1 = acc[ma][na][half * 2 + 1];
                if (MODE == 0) {
                    if (col0 < Ncol)
                        Cf[(size_t)row * Ncol + col0] = fmaxf(v0 + bias[col0], 0.f);
                    if (col0 + 1 < Ncol)
                        Cf[(size_t)row * Ncol + col0 + 1] = fmaxf(v1 + bias[col0 + 1], 0.f);
                } else if (MODE == 1) {
                    if (col0 < Ncol) Cf[(size_t)row * Ncol + col0] = v0;
                    if (col0 + 1 < Ncol) Cf[(size_t)row * Ncol + col0 + 1] = v1;
                } else if (MODE == 2) {
                    int b = row >> 10;          // row = b*P + p, P = 1024
                    int pp = row & 1023;
                    int p0 = pairs[(b * P + pp) * 2 + 0];
                    int p1 = pairs[(b * P + pp) * 2 + 1];
                    const float* ga = gAB + (size_t)(b * NE + p0) * (2 * HID);
                    const float* gb = gAB + (size_t)(b * NE + p1) * (2 * HID) + HID;
                    float r0 = fmaxf(v0 + ga[col0] + gb[col0] + bias[col0], 0.f);
                    float r1 = fmaxf(v1 + ga[col0 + 1] + gb[col0 + 1] + bias[col0 + 1], 0.f);
                    __nv_bfloat16 h0, l0, h1, l1;
                    split_bf16(r0, h0, l0);
                    split_bf16(r1, h1, l1);
                    size_t o = (size_t)row * HID + col0;
                    *reinterpret_cast<uint32_t*>(Chi + o) = pkbf(h0, h1);
                    *reinterpret_cast<uint32_t*>(Clo + o) = pkbf(l0, l1);
                } else {  // MODE 3
                    if (col0 < Ncol)
                        Cf[(size_t)row * Ncol + col0] = v0 + bias[col0];
                    if (col0 + 1 < Ncol)
                        Cf[(size_t)row * Ncol + col0 + 1] = v1 + bias[col0 + 1];
                }
            }
        }
    }
}

// ---------------- weight transpose + split: W[k][n] -> WT_hi/lo[n][k] ----------------
__global__ void k_transW(const float* __restrict__ W0, const float* __restrict__ Wsf,
                         int Ksplit, int K, int Nsrc,
                         __nv_bfloat16* __restrict__ Thi, __nv_bfloat16* __restrict__ Tlo) {
    __shared__ float t[32][33];
    int k0 = blockIdx.x * 32, n0 = blockIdx.y * 32;
    int tx = threadIdx.x, ty = threadIdx.y;
#pragma unroll
    for (int i = 0; i < 4; i++) {
        int k = k0 + ty + i * 8;
        int n = n0 + tx;
        const float* row = (k < Ksplit) ? W0 + (size_t)k * Nsrc
                                        : Wsf + (size_t)(k - Ksplit) * Nsrc;
        t[ty + i * 8][tx] = (n < Nsrc) ? row[n] : 0.f;
    }
    __syncthreads();
#pragma unroll
    for (int i = 0; i < 4; i++) {
        int n = n0 + ty + i * 8;
        int k = k0 + tx;
        float v = t[tx][ty + i * 8];
        __nv_bfloat16 h, l;
        split_bf16(v, h, l);
        Thi[(size_t)n * K + k] = h;
        Tlo[(size_t)n * K + k] = l;
    }
}

// ---------------- f32 -> hi/lo bf16 (flat, len % 4 == 0) ----------------
__global__ void k_convA(const float* __restrict__ in, __nv_bfloat16* __restrict__ hi,
                        __nv_bfloat16* __restrict__ lo) {
    size_t i = (size_t)blockIdx.x * blockDim.x + threadIdx.x;
    float4 v = reinterpret_cast<const float4*>(in)[i];
    __nv_bfloat16 hx, lx, hy, ly, hz, lz, hw, lw;
    split_bf16(v.x, hx, lx); split_bf16(v.y, hy, ly);
    split_bf16(v.z, hz, lz); split_bf16(v.w, hw, lw);
    reinterpret_cast<uint2*>(hi)[i] = make_uint2(pkbf(hx, hy), pkbf(hz, hw));
    reinterpret_cast<uint2*>(lo)[i] = make_uint2(pkbf(lx, ly), pkbf(lz, lw));
}

// ---------------- doc projection ----------------
__global__ void k_docproj(const float* __restrict__ cls, const float* __restrict__ W,
                          const float* __restrict__ bvec, float* __restrict__ out) {
    using namespace cfg;
    int b = blockIdx.y;
    int d = blockIdx.x * blockDim.x + threadIdx.x;
    if (d >= D) return;
    float acc = bvec[d];
    const float* c = cls + b * H;
    for (int h = 0; h < H; h++) acc = fmaf(c[h], W[(size_t)h * D + d], acc);
    out[b * D + d] = fmaxf(acc, 0.f);
}

// ---------------- node features h0 ----------------
__global__ void k_node(const float* __restrict__ token, const float* __restrict__ cls,
                       const int* __restrict__ pos, const float* __restrict__ smask,
                       const int* __restrict__ ner, const float* __restrict__ nmask,
                       const int* __restrict__ ment, const float* __restrict__ nerEmb,
                       const float* __restrict__ docproj, float* __restrict__ h0) {
    using namespace cfg;
    const int n = blockIdx.x, b = blockIdx.y;
    __shared__ int sp[S];
    __shared__ float sm[S];
    int tid = threadIdx.x;
    if (tid < S) {
        sp[tid] = pos[(b * N + n) * S + tid];
        sm[tid] = smask[(b * N + n) * S + tid];
    }
    __syncthreads();
    float* dst = h0 + (size_t)(b * N + n) * D;
    if (n == ment[b]) {
        for (int d = tid; d < D; d += blockDim.x) dst[d] = docproj[b * D + d];
        return;
    }
    float den = 0.1f;
#pragma unroll
    for (int s = 0; s < S; s++) den += sm[s];
    float nm = nmask[b * N + n];
    int nerIdx = ner[b * N + n];
    for (int d = tid; d < D; d += blockDim.x) {
        float v;
        if (d < H) {
            float acc = 0.f;
#pragma unroll
            for (int s = 0; s < S; s++)
                acc = fmaf(token[((size_t)b * T + sp[s]) * H + d], sm[s], acc);
            v = acc / den + cls[b * H + d];
        } else {
            v = nerEmb[nerIdx * NERD + (d - H)];
        }
        dst[d] = v * nm;
    }
}

// ---------------- init A buffer: slots 0..14 = 0, slot 15 = h ----------------
__global__ void k_initA(const float* __restrict__ hin, float* __restrict__ A) {
    using namespace cfg;
    size_t idx = (size_t)blockIdx.x * blockDim.x + threadIdx.x;
    int d = (int)(idx % D);
    size_t rest = idx / D;
    int r = (int)(rest & 15);
    size_t bn = rest >> 4;
    A[idx] = (r == 15) ? hin[bn * D + d] : 0.f;
}

// ---------------- edge scatter: A[b,dst,rel,:] += h[b,src,:] ----------------
__global__ void k_scatter(const float* __restrict__ hin, const int* __restrict__ src,
                          const int* __restrict__ dst, const int* __restrict__ rel,
                          float* __restrict__ A) {
    using namespace cfg;
    int e = blockIdx.x, b = blockIdx.y;
    int sIdx = src[b * E + e];
    int dIdx = dst[b * E + e];
    int r = rel[b * E + e];
    const float* hrow = hin + (size_t)(b * N + sIdx) * D;
    float* arow = A + ((size_t)(b * N + dIdx) * 16 + r) * D;
    for (int d = threadIdx.x; d < D; d += blockDim.x)
        atomicAdd(&arow[d], hrow[d]);
}

// ---------------- entity pooling -> hi/lo bf16 ----------------
__global__ void k_ent(const float* __restrict__ h1, const float* __restrict__ h2,
                      const int* __restrict__ e2m, const float* __restrict__ e2mask,
                      __nv_bfloat16* __restrict__ enthi, __nv_bfloat16* __restrict__ entlo) {
    using namespace cfg;
    int i = blockIdx.x, b = blockIdx.y;
    __shared__ int idxs[MM];
    __shared__ float mk[MM];
    int tid = threadIdx.x;
    if (tid < MM) {
        idxs[tid] = e2m[(b * NE + i) * MM + tid];
        mk[tid] = e2mask[(b * NE + i) * MM + tid];
    }
    __syncthreads();
    float den = 1e-7f;
#pragma unroll
    for (int j = 0; j < MM; j++) den += mk[j];
    for (int c = tid; c < EE; c += blockDim.x) {
        float acc = 0.f;
#pragma unroll
        for (int j = 0; j < MM; j++) {
            int id = idxs[j];
            if (id > 0) {
                float v = (c < D) ? h1[(size_t)(b * N + id - 1) * D + c]
                                  : h2[(size_t)(b * N + id - 1) * D + (c - D)];
                acc = fmaf(v, mk[j], acc);
            }
        }
        float r = acc / den;
        __nv_bfloat16 h, l;
        split_bf16(r, h, l);
        enthi[(size_t)(b * NE + i) * EE + c] = h;
        entlo[(size_t)(b * NE + i) * EE + c] = l;
    }
}

// ---------------- per-pair nonlinear features -> hi/lo bf16 ----------------
__global__ void k_nl(const __nv_bfloat16* __restrict__ enthi,
                     const __nv_bfloat16* __restrict__ entlo,
                     const int* __restrict__ pairs,
                     __nv_bfloat16* __restrict__ nlhi, __nv_bfloat16* __restrict__ nllo) {
    using namespace cfg;
    int p = blockIdx.x, b = blockIdx.y;
    int p0 = pairs[(b * P + p) * 2 + 0];
    int p1 = pairs[(b * P + p) * 2 + 1];
    const __nv_bfloat16* hfh = enthi + (size_t)(b * NE + p0) * EE;
    const __nv_bfloat16* hfl = entlo + (size_t)(b * NE + p0) * EE;
    const __nv_bfloat16* tfh = enthi + (size_t)(b * NE + p1) * EE;
    const __nv_bfloat16* tfl = entlo + (size_t)(b * NE + p1) * EE;
    size_t base = ((size_t)b * P + p) * HID;
    for (int c = threadIdx.x; c < EE; c += blockDim.x) {
        float a = __bfloat162float(hfh[c]) + __bfloat162float(hfl[c]);
        float t = __bfloat162float(tfh[c]) + __bfloat162float(tfl[c]);
        float d0 = fabsf(a - t);
        float d1 = a * t;
        __nv_bfloat16 h, l;
        split_bf16(d0, h, l);
        nlhi[base + c] = h; nllo[base + c] = l;
        split_bf16(d1, h, l);
        nlhi[base + EE + c] = h; nllo[base + EE + c] = l;
    }
}

// ---------------- launch ----------------
extern "C" void kernel_launch(void* const* d_in, const int* in_sizes, int n_in,
                              void* d_out, int out_size) {
    using namespace cfg;
    const float* token     = (const float*)d_in[0];
    const float* cls       = (const float*)d_in[1];
    const int*   span_pos  = (const int*)d_in[2];
    const float* span_mask = (const float*)d_in[3];
    const int*   node_ner  = (const int*)d_in[4];
    const float* node_mask = (const float*)d_in[5];
    const int*   e2m       = (const int*)d_in[6];
    const float* e2m_mask  = (const float*)d_in[7];
    const int*   ent_pair  = (const int*)d_in[8];
    const int*   edge_src  = (const int*)d_in[9];
    const int*   edge_dst  = (const int*)d_in[10];
    const int*   edge_rel  = (const int*)d_in[11];
    const int*   ment_num  = (const int*)d_in[12];
    const float* nerEmb    = (const float*)d_in[13];
    const float* doc_W     = (const float*)d_in[14];
    const float* doc_b     = (const float*)d_in[15];
    const float* W_rel     = (const float*)d_in[16];
    const float* W_self    = (const float*)d_in[17];
    const float* gnn_b     = (const float*)d_in[18];
    const float* W1        = (const float*)d_in[19];
    const float* b1        = (const float*)d_in[20];
    const float* W2        = (const float*)d_in[21];
    const float* b2        = (const float*)d_in[22];
    float* out = (float*)d_out;
    (void)in_sizes; (void)n_in; (void)out_size;

    float *pdoc, *ph0, *ph1, *ph2, *pA, *pentAB;
    __nv_bfloat16 *pAhi, *pAlo, *pWgT_hi, *pWgT_lo, *penthi, *pentlo;
    __nv_bfloat16 *pW1linT_hi, *pW1linT_lo, *pW1nlT_hi, *pW1nlT_lo, *pW2T_hi, *pW2T_lo;
    __nv_bfloat16 *pnlhi, *pnllo, *phidhi, *phidlo;
    cudaGetSymbolAddress((void**)&pdoc,  g_docproj);
    cudaGetSymbolAddress((void**)&ph0,   g_h0);
    cudaGetSymbolAddress((void**)&ph1,   g_h1);
    cudaGetSymbolAddress((void**)&ph2,   g_h2);
    cudaGetSymbolAddress((void**)&pA,    g_A);
    cudaGetSymbolAddress((void**)&pAhi,  g_Ahi);
    cudaGetSymbolAddress((void**)&pAlo,  g_Alo);
    cudaGetSymbolAddress((void**)&pWgT_hi, g_WgT_hi);
    cudaGetSymbolAddress((void**)&pWgT_lo, g_WgT_lo);
    cudaGetSymbolAddress((void**)&penthi, g_enthi);
    cudaGetSymbolAddress((void**)&pentlo, g_entlo);
    cudaGetSymbolAddress((void**)&pW1linT_hi, g_W1linT_hi);
    cudaGetSymbolAddress((void**)&pW1linT_lo, g_W1linT_lo);
    cudaGetSymbolAddress((void**)&pW1nlT_hi, g_W1nlT_hi);
    cudaGetSymbolAddress((void**)&pW1nlT_lo, g_W1nlT_lo);
    cudaGetSymbolAddress((void**)&pW2T_hi, g_W2T_hi);
    cudaGetSymbolAddress((void**)&pW2T_lo, g_W2T_lo);
    cudaGetSymbolAddress((void**)&pentAB, g_entAB);
    cudaGetSymbolAddress((void**)&pnlhi, g_nlhi);
    cudaGetSymbolAddress((void**)&pnllo, g_nllo);
    cudaGetSymbolAddress((void**)&phidhi, g_hidhi);
    cudaGetSymbolAddress((void**)&phidlo, g_hidlo);

    constexpr int SMEM64  = 2 * (2 * 128 * 128 + 2 * 64 * 128);    // 98304
    constexpr int SMEM128 = 2 * (2 * 128 * 128 + 2 * 128 * 128);   // 131072
    cudaFuncSetAttribute(k_mm<64, 0>,  cudaFuncAttributeMaxDynamicSharedMemorySize, SMEM64);
    cudaFuncSetAttribute(k_mm<128, 1>, cudaFuncAttributeMaxDynamicSharedMemorySize, SMEM128);
    cudaFuncSetAttribute(k_mm<128, 2>, cudaFuncAttributeMaxDynamicSharedMemorySize, SMEM128);
    cudaFuncSetAttribute(k_mm<64, 3>,  cudaFuncAttributeMaxDynamicSharedMemorySize, SMEM64);

    const dim3 tb(32, 8);

    // 0) one-shot weight transpose + split (per launch)
    k_transW<<<dim3(KG / 32, D / 32), tb>>>(W_rel, W_self, KSPLIT, KG, D,
                                            pWgT_hi, pWgT_lo);
    k_transW<<<dim3(KG / 32, D / 32), tb>>>(W_rel + (size_t)R * D * D,
                                            W_self + (size_t)D * D, KSPLIT, KG, D,
                                            pWgT_hi + (size_t)NPG * KG,
                                            pWgT_lo + (size_t)NPG * KG);
    k_transW<<<dim3(EE / 32, HID / 32), tb>>>(W1, W1, EE, EE, HID,
                                              pW1linT_hi, pW1linT_lo);
    k_transW<<<dim3(EE / 32, HID / 32), tb>>>(W1 + (size_t)EE * HID, W1, EE, EE, HID,
                                              pW1linT_hi + (size_t)HID * EE,
                                              pW1linT_lo + (size_t)HID * EE);
    k_transW<<<dim3(HID / 32, HID / 32), tb>>>(W1 + (size_t)2 * EE * HID, W1, HID,
                                               HID, HID, pW1nlT_hi, pW1nlT_lo);
    k_transW<<<dim3(HID / 32, 4), tb>>>(W2, W2, HID, HID, OUT, pW2T_hi, pW2T_lo);

    // 1) doc projection + node features
    k_docproj<<<dim3((D + 255) / 256, B), 256>>>(cls, doc_W, doc_b, pdoc);
    k_node<<<dim3(N, B), 256>>>(token, cls, span_pos, span_mask, node_ner, node_mask,
                                ment_num, nerEmb, pdoc, ph0);

    const size_t Atotal = (size_t)B * N * 16 * D;   // 13,107,200
    const int initBlocks = (int)(Atotal / 256);
    const int convBlocks = (int)(Atotal / 4 / 256);

    // 2) GNN layer 0
    k_initA<<<initBlocks, 256>>>(ph0, pA);
    k_scatter<<<dim3(E, B), 256>>>(ph0, edge_src, edge_dst, edge_rel, pA);
    k_convA<<<convBlocks, 256>>>(pA, pAhi, pAlo);
    k_mm<64, 0><<<dim3(NPG / 64, (B * N) / 128), 256, SMEM64>>>(
        pAhi, pAlo, pWgT_hi, pWgT_lo, KG, D, gnn_b, ph1,
        nullptr, nullptr, nullptr, nullptr);

    // 3) GNN layer 1
    k_initA<<<initBlocks, 256>>>(ph1, pA);
    k_scatter<<<dim3(E, B), 256>>>(ph1, edge_src, edge_dst, edge_rel, pA);
    k_convA<<<convBlocks, 256>>>(pA, pAhi, pAlo);
    k_mm<64, 0><<<dim3(NPG / 64, (B * N) / 128), 256, SMEM64>>>(
        pAhi, pAlo, pWgT_hi + (size_t)NPG * KG, pWgT_lo + (size_t)NPG * KG,
        KG, D, gnn_b + D, ph2, nullptr, nullptr, nullptr, nullptr);

    // 4) entity pooling (-> hi/lo)
    k_ent<<<dim3(NE, B), 256>>>(ph1, ph2, e2m, e2m_mask, penthi, pentlo);

    // 5) linear halves of pair MLP in one GEMM: entAB[256][6400]
    k_mm<128, 1><<<dim3((2 * HID) / 128, (B * NE) / 128), 256, SMEM128>>>(
        penthi, pentlo, pW1linT_hi, pW1linT_lo, EE, 2 * HID, nullptr, pentAB,
        nullptr, nullptr, nullptr, nullptr);

    // 6) nonlinear pair features + big GEMM with fused gather epilogue -> hid hi/lo
    k_nl<<<dim3(P, B), 256>>>(penthi, pentlo, ent_pair, pnlhi, pnllo);
    k_mm<128, 2><<<dim3(HID / 128, (B * P) / 128), 256, SMEM128>>>(
        pnlhi, pnllo, pW1nlT_hi, pW1nlT_lo, HID, HID, b1, nullptr,
        phidhi, phidlo, pentAB, ent_pair);

    // 7) output layer: hidden @ W2 + b2
    k_mm<64, 3><<<dim3(2, (B * P) / 128), 256, SMEM64>>>(
        phidhi, phidlo, pW2T_hi, pW2T_lo, HID, OUT, b2, out,
        nullptr, nullptr, nullptr, nullptr);
}

// round 6
// speedup vs baseline: 3.3788x; 1.1111x over previous
#include <cuda_runtime.h>
#include <cuda_bf16.h>
#include <cstdint>
#include <cstddef>

namespace cfg {
constexpr int B = 4;
constexpr int T = 512;
constexpr int H = 768;
constexpr int N = 256;
constexpr int S = 16;
constexpr int NERD = 32;
constexpr int D = 800;          // H + NERD
constexpr int R = 15;
constexpr int NE = 64;
constexpr int MM = 8;
constexpr int P = 1024;
constexpr int E = 4096;
constexpr int OUT = 97;
constexpr int EE = 1600;        // 2*D
constexpr int HID = 3200;       // 2*EE
constexpr int KG = 12800;       // 16*D  ([S_0..S_14 | h])
constexpr int KSPLIT = 12000;   // R*D
constexpr int NPG = 832;        // GNN N padded to 13*64
}

// ---------------- scratch (device globals; no runtime allocation) ----------------
__device__ float g_docproj[cfg::B * cfg::D];
__device__ float g_h0[cfg::B * cfg::N * cfg::D];
__device__ float g_h1[cfg::B * cfg::N * cfg::D];
__device__ float g_h2[cfg::B * cfg::N * cfg::D];
__device__ float g_A[(size_t)cfg::B * cfg::N * 16 * cfg::D];             // 52 MB f32
__device__ __nv_bfloat16 g_Ahi[(size_t)cfg::B * cfg::N * 16 * cfg::D];
__device__ __nv_bfloat16 g_Alo[(size_t)cfg::B * cfg::N * 16 * cfg::D];
__device__ __nv_bfloat16 g_WgT_hi[2][(size_t)cfg::NPG * cfg::KG];
__device__ __nv_bfloat16 g_WgT_lo[2][(size_t)cfg::NPG * cfg::KG];
__device__ __nv_bfloat16 g_enthi[cfg::B * cfg::NE * cfg::EE];
__device__ __nv_bfloat16 g_entlo[cfg::B * cfg::NE * cfg::EE];
__device__ __nv_bfloat16 g_W1linT_hi[(size_t)2 * cfg::HID * cfg::EE];    // [6400][1600]
__device__ __nv_bfloat16 g_W1linT_lo[(size_t)2 * cfg::HID * cfg::EE];
__device__ __nv_bfloat16 g_W1nlT_hi[(size_t)cfg::HID * cfg::HID];        // [3200][3200]
__device__ __nv_bfloat16 g_W1nlT_lo[(size_t)cfg::HID * cfg::HID];
__device__ __nv_bfloat16 g_W2T_hi[128 * cfg::HID];
__device__ __nv_bfloat16 g_W2T_lo[128 * cfg::HID];
__device__ float g_entAB[(size_t)cfg::B * cfg::NE * 2 * cfg::HID];       // [256][6400]
__device__ __nv_bfloat16 g_nlhi[(size_t)cfg::B * cfg::P * cfg::HID];
__device__ __nv_bfloat16 g_nllo[(size_t)cfg::B * cfg::P * cfg::HID];
__device__ __nv_bfloat16 g_hidhi[(size_t)cfg::B * cfg::P * cfg::HID];
__device__ __nv_bfloat16 g_hidlo[(size_t)cfg::B * cfg::P * cfg::HID];
__device__ float g_gnnacc[(size_t)cfg::B * cfg::N * cfg::NPG];           // split-K accum
__device__ float g_outacc[(size_t)cfg::B * cfg::P * cfg::OUT];

// ================= helpers =================
__device__ __forceinline__ uint32_t smem_u32(const void* p) {
    uint32_t a;
    asm("{ .reg .u64 t; cvta.to.shared.u64 t, %1; cvt.u32.u64 %0, t; }"
        : "=r"(a) : "l"(p));
    return a;
}
__device__ __forceinline__ void ldsm4(uint32_t* r, uint32_t addr) {
    asm volatile("ldmatrix.sync.aligned.m8n8.x4.shared.b16 {%0,%1,%2,%3}, [%4];"
                 : "=r"(r[0]), "=r"(r[1]), "=r"(r[2]), "=r"(r[3]) : "r"(addr));
}
__device__ __forceinline__ void mma_bf16(float* c, const uint32_t* a,
                                         uint32_t b0, uint32_t b1) {
    asm volatile(
        "mma.sync.aligned.m16n8k16.row.col.f32.bf16.bf16.f32 "
        "{%0,%1,%2,%3}, {%4,%5,%6,%7}, {%8,%9}, {%0,%1,%2,%3};"
        : "+f"(c[0]), "+f"(c[1]), "+f"(c[2]), "+f"(c[3])
        : "r"(a[0]), "r"(a[1]), "r"(a[2]), "r"(a[3]), "r"(b0), "r"(b1));
}
__device__ __forceinline__ void split_bf16(float x, __nv_bfloat16& h, __nv_bfloat16& l) {
    h = __float2bfloat16_rn(x);
    l = __float2bfloat16_rn(x - __bfloat162float(h));
}
__device__ __forceinline__ uint32_t pkbf(__nv_bfloat16 a, __nv_bfloat16 b) {
    __nv_bfloat162 t = __halves2bfloat162(a, b);
    return *reinterpret_cast<uint32_t*>(&t);
}
__device__ __forceinline__ void cpa16(uint32_t dst, const void* src) {
    asm volatile("cp.async.cg.shared.global [%0], [%1], 16;" :: "r"(dst), "l"(src));
}
__device__ __forceinline__ void cpa_commit() {
    asm volatile("cp.async.commit_group;" ::: "memory");
}
template <int NN>
__device__ __forceinline__ void cpa_wait() {
    asm volatile("cp.async.wait_group %0;" :: "n"(NN) : "memory");
}

// =====================================================================
// Double-buffered split-bf16 HMMA GEMM (split-K capable).
//   A: hi/lo bf16 [M][Kstride].  B: hi/lo bf16 [N][Kstride] (W^T).
//   This block handles K-range [blockIdx.z*Klen, (blockIdx.z+1)*Klen).
// MODE 2: v = relu(acc + gAB[p0,col] + gAB[p1,HID+col] + bias[col]) -> Chi/Clo (z=1)
// MODE 4: atomicAdd(Cf[row][col], acc)
// =====================================================================
template <int BN, int MODE>
__global__ void __launch_bounds__(256)
k_mm(const __nv_bfloat16* __restrict__ Ahi, const __nv_bfloat16* __restrict__ Alo,
     const __nv_bfloat16* __restrict__ Bhi, const __nv_bfloat16* __restrict__ Blo,
     int Kstride, int Klen, int Ncol,
     const float* __restrict__ bias, float* __restrict__ Cf,
     __nv_bfloat16* __restrict__ Chi, __nv_bfloat16* __restrict__ Clo,
     const float* __restrict__ gAB, const int* __restrict__ pairs) {
    using namespace cfg;
    constexpr int BM = 128, BK = 64;
    constexpr int WNG = (BN == 128) ? 4 : 2;
    constexpr int WMG = 8 / WNG;
    constexpr int WTM = BM / WMG;        // 64 or 32
    constexpr int WTN = BN / WNG;        // 32
    constexpr int MATOMS = WTM / 16;
    constexpr int NAT16 = WTN / 16;      // 2
    constexpr int NATOMS = WTN / 8;      // 4
    constexpr int RB = BM * 128;         // bytes of one A half-tile
    constexpr int RBB = BN * 128;        // bytes of one B half-tile
    constexpr int SB = 2 * RB + 2 * RBB; // stage bytes

    extern __shared__ char smem[];
    const uint32_t sbase = smem_u32(smem);
    const int tid = threadIdx.x;
    const int wid = tid >> 5, lane = tid & 31;
    const int wn = wid % WNG, wm = wid / WNG;
    const int bm0 = blockIdx.y * BM, bn0 = blockIdx.x * BN;
    const int lrow = lane & 15, lhalf = lane >> 4;
    const int kofs = blockIdx.z * Klen;

    float acc[MATOMS][NATOMS][4];
#pragma unroll
    for (int i = 0; i < MATOMS; i++)
#pragma unroll
        for (int j = 0; j < NATOMS; j++)
#pragma unroll
            for (int q = 0; q < 4; q++) acc[i][j][q] = 0.f;

    const __nv_bfloat16* Ah = Ahi + (size_t)bm0 * Kstride + kofs;
    const __nv_bfloat16* Al = Alo + (size_t)bm0 * Kstride + kofs;
    const __nv_bfloat16* Bh = Bhi + (size_t)bn0 * Kstride + kofs;
    const __nv_bfloat16* Bl = Blo + (size_t)bn0 * Kstride + kofs;

    auto load_stage = [&](int s, int k0) {
        uint32_t base = sbase + s * SB;
#pragma unroll
        for (int i = 0; i < BM * 8 / 256; i++) {
            int f = tid + i * 256;
            int row = f >> 3, g = f & 7;
            uint32_t d = base + row * 128 + ((g ^ (row & 7)) << 4);
            size_t so = (size_t)row * Kstride + k0 + g * 8;
            cpa16(d, Ah + so);
            cpa16(d + RB, Al + so);
        }
#pragma unroll
        for (int i = 0; i < BN * 8 / 256; i++) {
            int f = tid + i * 256;
            int row = f >> 3, g = f & 7;
            uint32_t d = base + 2 * RB + row * 128 + ((g ^ (row & 7)) << 4);
            size_t so = (size_t)row * Kstride + k0 + g * 8;
            cpa16(d, Bh + so);
            cpa16(d + RBB, Bl + so);
        }
    };

    const int nch = Klen / BK;
    load_stage(0, 0);
    cpa_commit();

    for (int ch = 0; ch < nch; ch++) {
        if (ch + 1 < nch) {
            load_stage((ch + 1) & 1, (ch + 1) * BK);
            cpa_commit();
            cpa_wait<1>();
        } else {
            cpa_wait<0>();
        }
        __syncthreads();

        uint32_t sA = sbase + (ch & 1) * SB;
        uint32_t sB = sA + 2 * RB;
#pragma unroll
        for (int s = 0; s < 4; s++) {
            uint32_t ah[MATOMS][4], al[MATOMS][4];
#pragma unroll
            for (int ma = 0; ma < MATOMS; ma++) {
                int row = wm * WTM + ma * 16 + lrow;
                uint32_t off = sA + row * 128 + (((s * 2 + lhalf) ^ (row & 7)) << 4);
                ldsm4(ah[ma], off);
                ldsm4(al[ma], off + RB);
            }
            uint32_t bh[NAT16][4], bl[NAT16][4];
#pragma unroll
            for (int ng = 0; ng < NAT16; ng++) {
                int rb = wn * WTN + ng * 16 + lrow;
                uint32_t off = sB + rb * 128 + (((s * 2 + lhalf) ^ (rb & 7)) << 4);
                ldsm4(bh[ng], off);
                ldsm4(bl[ng], off + RBB);
            }
#pragma unroll
            for (int ma = 0; ma < MATOMS; ma++)
#pragma unroll
                for (int na = 0; na < NATOMS; na++)
                    mma_bf16(acc[ma][na], ah[ma], bh[na >> 1][na & 1],
                             bh[na >> 1][2 + (na & 1)]);
#pragma unroll
            for (int ma = 0; ma < MATOMS; ma++)
#pragma unroll
                for (int na = 0; na < NATOMS; na++)
                    mma_bf16(acc[ma][na], ah[ma], bl[na >> 1][na & 1],
                             bl[na >> 1][2 + (na & 1)]);
#pragma unroll
            for (int ma = 0; ma < MATOMS; ma++)
#pragma unroll
                for (int na = 0; na < NATOMS; na++)
                    mma_bf16(acc[ma][na], al[ma], bh[na >> 1][na & 1],
                             bh[na >> 1][2 + (na & 1)]);
        }
        __syncthreads();
    }

    // ---- epilogue ----
    const int gid = lane >> 2, tig = lane & 3;
#pragma unroll
    for (int ma = 0; ma < MATOMS; ma++) {
        int rowbase = bm0 + wm * WTM + ma * 16;
#pragma unroll
        for (int na = 0; na < NATOMS; na++) {
            int col0 = bn0 + wn * WTN + na * 8 + 2 * tig;
#pragma unroll
            for (int half = 0; half < 2; half++) {
                int row = rowbase + gid + half * 8;
                float v0 = acc[ma][na][half * 2 + 0];
                float v1 = acc[ma][na][half * 2 + 1];
                if (MODE == 2) {
                    int b = row >> 10;          // row = b*P + p, P = 1024
                    int pp = row & 1023;
                    int p0 = pairs[(b * P + pp) * 2 + 0];
                    int p1 = pairs[(b * P + pp) * 2 + 1];
                    const float* ga = gAB + (size_t)(b * NE + p0) * (2 * HID);
                    const float* gb = gAB + (size_t)(b * NE + p1) * (2 * HID) + HID;
                    float r0 = fmaxf(v0 + ga[col0] + gb[col0] + bias[col0], 0.f);
                    float r1 = fmaxf(v1 + ga[col0 + 1] + gb[col0 + 1] + bias[col0 + 1], 0.f);
                    __nv_bfloat16 h0, l0, h1, l1;
                    split_bf16(r0, h0, l0);
                    split_bf16(r1, h1, l1);
                    size_t o = (size_t)row * HID + col0;
                    *reinterpret_cast<uint32_t*>(Chi + o) = pkbf(h0, h1);
                    *reinterpret_cast<uint32_t*>(Clo + o) = pkbf(l0, l1);
                } else {  // MODE 4: split-K atomic accumulate
                    if (col0 < Ncol)
                        atomicAdd(&Cf[(size_t)row * Ncol + col0], v0);
                    if (col0 + 1 < Ncol)
                        atomicAdd(&Cf[(size_t)row * Ncol + col0 + 1], v1);
                }
            }
        }
    }
}

// ---------------- zero f32 buffer (len % 4 == 0) ----------------
__global__ void k_zero(float* __restrict__ p, int n4) {
    int i = blockIdx.x * blockDim.x + threadIdx.x;
    if (i < n4) reinterpret_cast<float4*>(p)[i] = make_float4(0.f, 0.f, 0.f, 0.f);
}

// ---------------- GNN epilogue: h = relu(acc + bias), acc [rows][NPG] -> [rows][D] ----------------
__global__ void k_epignn(const float* __restrict__ acc, const float* __restrict__ bias,
                         float* __restrict__ h) {
    using namespace cfg;
    int i = blockIdx.x * blockDim.x + threadIdx.x;   // over B*N*D
    int row = i / D, col = i - row * D;
    h[i] = fmaxf(acc[(size_t)row * NPG + col] + bias[col], 0.f);
}

// ---------------- out epilogue: out = acc + b2 ----------------
__global__ void k_epiout(const float* __restrict__ acc, const float* __restrict__ b2,
                         float* __restrict__ out, int total) {
    using namespace cfg;
    int i = blockIdx.x * blockDim.x + threadIdx.x;
    if (i < total) out[i] = acc[i] + b2[i % OUT];
}

// ---------------- weight transpose + split: W[k][n] -> WT_hi/lo[n][k] ----------------
__global__ void k_transW(const float* __restrict__ W0, const float* __restrict__ Wsf,
                         int Ksplit, int K, int Nsrc,
                         __nv_bfloat16* __restrict__ Thi, __nv_bfloat16* __restrict__ Tlo) {
    __shared__ float t[32][33];
    int k0 = blockIdx.x * 32, n0 = blockIdx.y * 32;
    int tx = threadIdx.x, ty = threadIdx.y;
#pragma unroll
    for (int i = 0; i < 4; i++) {
        int k = k0 + ty + i * 8;
        int n = n0 + tx;
        const float* row = (k < Ksplit) ? W0 + (size_t)k * Nsrc
                                        : Wsf + (size_t)(k - Ksplit) * Nsrc;
        t[ty + i * 8][tx] = (n < Nsrc) ? row[n] : 0.f;
    }
    __syncthreads();
#pragma unroll
    for (int i = 0; i < 4; i++) {
        int n = n0 + ty + i * 8;
        int k = k0 + tx;
        float v = t[tx][ty + i * 8];
        __nv_bfloat16 h, l;
        split_bf16(v, h, l);
        Thi[(size_t)n * K + k] = h;
        Tlo[(size_t)n * K + k] = l;
    }
}

// ---------------- f32 -> hi/lo bf16 (flat, len % 4 == 0) ----------------
__global__ void k_convA(const float* __restrict__ in, __nv_bfloat16* __restrict__ hi,
                        __nv_bfloat16* __restrict__ lo) {
    size_t i = (size_t)blockIdx.x * blockDim.x + threadIdx.x;
    float4 v = reinterpret_cast<const float4*>(in)[i];
    __nv_bfloat16 hx, lx, hy, ly, hz, lz, hw, lw;
    split_bf16(v.x, hx, lx); split_bf16(v.y, hy, ly);
    split_bf16(v.z, hz, lz); split_bf16(v.w, hw, lw);
    reinterpret_cast<uint2*>(hi)[i] = make_uint2(pkbf(hx, hy), pkbf(hz, hw));
    reinterpret_cast<uint2*>(lo)[i] = make_uint2(pkbf(lx, ly), pkbf(lz, lw));
}

// ---------------- doc projection ----------------
__global__ void k_docproj(const float* __restrict__ cls, const float* __restrict__ W,
                          const float* __restrict__ bvec, float* __restrict__ out) {
    using namespace cfg;
    int b = blockIdx.y;
    int d = blockIdx.x * blockDim.x + threadIdx.x;
    if (d >= D) return;
    float acc = bvec[d];
    const float* c = cls + b * H;
    for (int h = 0; h < H; h++) acc = fmaf(c[h], W[(size_t)h * D + d], acc);
    out[b * D + d] = fmaxf(acc, 0.f);
}

// ---------------- node features h0 ----------------
__global__ void k_node(const float* __restrict__ token, const float* __restrict__ cls,
                       const int* __restrict__ pos, const float* __restrict__ smask,
                       const int* __restrict__ ner, const float* __restrict__ nmask,
                       const int* __restrict__ ment, const float* __restrict__ nerEmb,
                       const float* __restrict__ docproj, float* __restrict__ h0) {
    using namespace cfg;
    const int n = blockIdx.x, b = blockIdx.y;
    __shared__ int sp[S];
    __shared__ float sm[S];
    int tid = threadIdx.x;
    if (tid < S) {
        sp[tid] = pos[(b * N + n) * S + tid];
        sm[tid] = smask[(b * N + n) * S + tid];
    }
    __syncthreads();
    float* dst = h0 + (size_t)(b * N + n) * D;
    if (n == ment[b]) {
        for (int d = tid; d < D; d += blockDim.x) dst[d] = docproj[b * D + d];
        return;
    }
    float den = 0.1f;
#pragma unroll
    for (int s = 0; s < S; s++) den += sm[s];
    float nm = nmask[b * N + n];
    int nerIdx = ner[b * N + n];
    for (int d = tid; d < D; d += blockDim.x) {
        float v;
        if (d < H) {
            float acc = 0.f;
#pragma unroll
            for (int s = 0; s < S; s++)
                acc = fmaf(token[((size_t)b * T + sp[s]) * H + d], sm[s], acc);
            v = acc / den + cls[b * H + d];
        } else {
            v = nerEmb[nerIdx * NERD + (d - H)];
        }
        dst[d] = v * nm;
    }
}

// ---------------- init A buffer: slots 0..14 = 0, slot 15 = h ----------------
__global__ void k_initA(const float* __restrict__ hin, float* __restrict__ A) {
    using namespace cfg;
    size_t idx = (size_t)blockIdx.x * blockDim.x + threadIdx.x;
    int d = (int)(idx % D);
    size_t rest = idx / D;
    int r = (int)(rest & 15);
    size_t bn = rest >> 4;
    A[idx] = (r == 15) ? hin[bn * D + d] : 0.f;
}

// ---------------- edge scatter: A[b,dst,rel,:] += h[b,src,:] ----------------
__global__ void k_scatter(const float* __restrict__ hin, const int* __restrict__ src,
                          const int* __restrict__ dst, const int* __restrict__ rel,
                          float* __restrict__ A) {
    using namespace cfg;
    int e = blockIdx.x, b = blockIdx.y;
    int sIdx = src[b * E + e];
    int dIdx = dst[b * E + e];
    int r = rel[b * E + e];
    const float* hrow = hin + (size_t)(b * N + sIdx) * D;
    float* arow = A + ((size_t)(b * N + dIdx) * 16 + r) * D;
    for (int d = threadIdx.x; d < D; d += blockDim.x)
        atomicAdd(&arow[d], hrow[d]);
}

// ---------------- entity pooling -> hi/lo bf16 ----------------
__global__ void k_ent(const float* __restrict__ h1, const float* __restrict__ h2,
                      const int* __restrict__ e2m, const float* __restrict__ e2mask,
                      __nv_bfloat16* __restrict__ enthi, __nv_bfloat16* __restrict__ entlo) {
    using namespace cfg;
    int i = blockIdx.x, b = blockIdx.y;
    __shared__ int idxs[MM];
    __shared__ float mk[MM];
    int tid = threadIdx.x;
    if (tid < MM) {
        idxs[tid] = e2m[(b * NE + i) * MM + tid];
        mk[tid] = e2mask[(b * NE + i) * MM + tid];
    }
    __syncthreads();
    float den = 1e-7f;
#pragma unroll
    for (int j = 0; j < MM; j++) den += mk[j];
    for (int c = tid; c < EE; c += blockDim.x) {
        float acc = 0.f;
#pragma unroll
        for (int j = 0; j < MM; j++) {
            int id = idxs[j];
            if (id > 0) {
                float v = (c < D) ? h1[(size_t)(b * N + id - 1) * D + c]
                                  : h2[(size_t)(b * N + id - 1) * D + (c - D)];
                acc = fmaf(v, mk[j], acc);
            }
        }
        float r = acc / den;
        __nv_bfloat16 h, l;
        split_bf16(r, h, l);
        enthi[(size_t)(b * NE + i) * EE + c] = h;
        entlo[(size_t)(b * NE + i) * EE + c] = l;
    }
}

// ---------------- per-pair nonlinear features -> hi/lo bf16 ----------------
__global__ void k_nl(const __nv_bfloat16* __restrict__ enthi,
                     const __nv_bfloat16* __restrict__ entlo,
                     const int* __restrict__ pairs,
                     __nv_bfloat16* __restrict__ nlhi, __nv_bfloat16* __restrict__ nllo) {
    using namespace cfg;
    int p = blockIdx.x, b = blockIdx.y;
    int p0 = pairs[(b * P + p) * 2 + 0];
    int p1 = pairs[(b * P + p) * 2 + 1];
    const __nv_bfloat16* hfh = enthi + (size_t)(b * NE + p0) * EE;
    const __nv_bfloat16* hfl = entlo + (size_t)(b * NE + p0) * EE;
    const __nv_bfloat16* tfh = enthi + (size_t)(b * NE + p1) * EE;
    const __nv_bfloat16* tfl = entlo + (size_t)(b * NE + p1) * EE;
    size_t base = ((size_t)b * P + p) * HID;
    for (int c = threadIdx.x; c < EE; c += blockDim.x) {
        float a = __bfloat162float(hfh[c]) + __bfloat162float(hfl[c]);
        float t = __bfloat162float(tfh[c]) + __bfloat162float(tfl[c]);
        float d0 = fabsf(a - t);
        float d1 = a * t;
        __nv_bfloat16 h, l;
        split_bf16(d0, h, l);
        nlhi[base + c] = h; nllo[base + c] = l;
        split_bf16(d1, h, l);
        nlhi[base + EE + c] = h; nllo[base + EE + c] = l;
    }
}

// ---------------- launch ----------------
extern "C" void kernel_launch(void* const* d_in, const int* in_sizes, int n_in,
                              void* d_out, int out_size) {
    using namespace cfg;
    const float* token     = (const float*)d_in[0];
    const float* cls       = (const float*)d_in[1];
    const int*   span_pos  = (const int*)d_in[2];
    const float* span_mask = (const float*)d_in[3];
    const int*   node_ner  = (const int*)d_in[4];
    const float* node_mask = (const float*)d_in[5];
    const int*   e2m       = (const int*)d_in[6];
    const float* e2m_mask  = (const float*)d_in[7];
    const int*   ent_pair  = (const int*)d_in[8];
    const int*   edge_src  = (const int*)d_in[9];
    const int*   edge_dst  = (const int*)d_in[10];
    const int*   edge_rel  = (const int*)d_in[11];
    const int*   ment_num  = (const int*)d_in[12];
    const float* nerEmb    = (const float*)d_in[13];
    const float* doc_W     = (const float*)d_in[14];
    const float* doc_b     = (const float*)d_in[15];
    const float* W_rel     = (const float*)d_in[16];
    const float* W_self    = (const float*)d_in[17];
    const float* gnn_b     = (const float*)d_in[18];
    const float* W1        = (const float*)d_in[19];
    const float* b1        = (const float*)d_in[20];
    const float* W2        = (const float*)d_in[21];
    const float* b2        = (const float*)d_in[22];
    float* out = (float*)d_out;
    (void)in_sizes; (void)n_in; (void)out_size;

    float *pdoc, *ph0, *ph1, *ph2, *pA, *pentAB, *pgnnacc, *poutacc;
    __nv_bfloat16 *pAhi, *pAlo, *pWgT_hi, *pWgT_lo, *penthi, *pentlo;
    __nv_bfloat16 *pW1linT_hi, *pW1linT_lo, *pW1nlT_hi, *pW1nlT_lo, *pW2T_hi, *pW2T_lo;
    __nv_bfloat16 *pnlhi, *pnllo, *phidhi, *phidlo;
    cudaGetSymbolAddress((void**)&pdoc,  g_docproj);
    cudaGetSymbolAddress((void**)&ph0,   g_h0);
    cudaGetSymbolAddress((void**)&ph1,   g_h1);
    cudaGetSymbolAddress((void**)&ph2,   g_h2);
    cudaGetSymbolAddress((void**)&pA,    g_A);
    cudaGetSymbolAddress((void**)&pAhi,  g_Ahi);
    cudaGetSymbolAddress((void**)&pAlo,  g_Alo);
    cudaGetSymbolAddress((void**)&pWgT_hi, g_WgT_hi);
    cudaGetSymbolAddress((void**)&pWgT_lo, g_WgT_lo);
    cudaGetSymbolAddress((void**)&penthi, g_enthi);
    cudaGetSymbolAddress((void**)&pentlo, g_entlo);
    cudaGetSymbolAddress((void**)&pW1linT_hi, g_W1linT_hi);
    cudaGetSymbolAddress((void**)&pW1linT_lo, g_W1linT_lo);
    cudaGetSymbolAddress((void**)&pW1nlT_hi, g_W1nlT_hi);
    cudaGetSymbolAddress((void**)&pW1nlT_lo, g_W1nlT_lo);
    cudaGetSymbolAddress((void**)&pW2T_hi, g_W2T_hi);
    cudaGetSymbolAddress((void**)&pW2T_lo, g_W2T_lo);
    cudaGetSymbolAddress((void**)&pentAB, g_entAB);
    cudaGetSymbolAddress((void**)&pnlhi, g_nlhi);
    cudaGetSymbolAddress((void**)&pnllo, g_nllo);
    cudaGetSymbolAddress((void**)&phidhi, g_hidhi);
    cudaGetSymbolAddress((void**)&phidlo, g_hidlo);
    cudaGetSymbolAddress((void**)&pgnnacc, g_gnnacc);
    cudaGetSymbolAddress((void**)&poutacc, g_outacc);

    constexpr int SMEM64  = 2 * (2 * 128 * 128 + 2 * 64 * 128);    // 98304
    constexpr int SMEM128 = 2 * (2 * 128 * 128 + 2 * 128 * 128);   // 131072
    cudaFuncSetAttribute(k_mm<64, 4>,  cudaFuncAttributeMaxDynamicSharedMemorySize, SMEM64);
    cudaFuncSetAttribute(k_mm<128, 4>, cudaFuncAttributeMaxDynamicSharedMemorySize, SMEM128);
    cudaFuncSetAttribute(k_mm<128, 2>, cudaFuncAttributeMaxDynamicSharedMemorySize, SMEM128);

    const dim3 tb(32, 8);

    // 0) one-shot weight transpose + split (per launch)
    k_transW<<<dim3(KG / 32, D / 32), tb>>>(W_rel, W_self, KSPLIT, KG, D,
                                            pWgT_hi, pWgT_lo);
    k_transW<<<dim3(KG / 32, D / 32), tb>>>(W_rel + (size_t)R * D * D,
                                            W_self + (size_t)D * D, KSPLIT, KG, D,
                                            pWgT_hi + (size_t)NPG * KG,
                                            pWgT_lo + (size_t)NPG * KG);
    k_transW<<<dim3(EE / 32, HID / 32), tb>>>(W1, W1, EE, EE, HID,
                                              pW1linT_hi, pW1linT_lo);
    k_transW<<<dim3(EE / 32, HID / 32), tb>>>(W1 + (size_t)EE * HID, W1, EE, EE, HID,
                                              pW1linT_hi + (size_t)HID * EE,
                                              pW1linT_lo + (size_t)HID * EE);
    k_transW<<<dim3(HID / 32, HID / 32), tb>>>(W1 + (size_t)2 * EE * HID, W1, HID,
                                               HID, HID, pW1nlT_hi, pW1nlT_lo);
    k_transW<<<dim3(HID / 32, 4), tb>>>(W2, W2, HID, HID, OUT, pW2T_hi, pW2T_lo);

    // 1) doc projection + node features
    k_docproj<<<dim3((D + 255) / 256, B), 256>>>(cls, doc_W, doc_b, pdoc);
    k_node<<<dim3(N, B), 256>>>(token, cls, span_pos, span_mask, node_ner, node_mask,
                                ment_num, nerEmb, pdoc, ph0);

    const size_t Atotal = (size_t)B * N * 16 * D;   // 13,107,200
    const int initBlocks = (int)(Atotal / 256);
    const int convBlocks = (int)(Atotal / 4 / 256);
    const int gnnaccN4 = B * N * NPG / 4;           // 212992
    const int entabN4 = B * NE * 2 * HID / 4;       // 409600
    const int outaccTotal = B * P * OUT;            // 397312
    const int gnnEpiBlocks = (B * N * D) / 256;     // 3200

    // 2) GNN layer 0 (split-K z=4 into gnnacc, then relu+bias epilogue)
    k_initA<<<initBlocks, 256>>>(ph0, pA);
    k_scatter<<<dim3(E, B), 256>>>(ph0, edge_src, edge_dst, edge_rel, pA);
    k_convA<<<convBlocks, 256>>>(pA, pAhi, pAlo);
    k_zero<<<(gnnaccN4 + 255) / 256, 256>>>(pgnnacc, gnnaccN4);
    k_mm<64, 4><<<dim3(NPG / 64, (B * N) / 128, 4), 256, SMEM64>>>(
        pAhi, pAlo, pWgT_hi, pWgT_lo, KG, KG / 4, NPG, nullptr, pgnnacc,
        nullptr, nullptr, nullptr, nullptr);
    k_epignn<<<gnnEpiBlocks, 256>>>(pgnnacc, gnn_b, ph1);

    // 3) GNN layer 1
    k_initA<<<initBlocks, 256>>>(ph1, pA);
    k_scatter<<<dim3(E, B), 256>>>(ph1, edge_src, edge_dst, edge_rel, pA);
    k_convA<<<convBlocks, 256>>>(pA, pAhi, pAlo);
    k_zero<<<(gnnaccN4 + 255) / 256, 256>>>(pgnnacc, gnnaccN4);
    k_mm<64, 4><<<dim3(NPG / 64, (B * N) / 128, 4), 256, SMEM64>>>(
        pAhi, pAlo, pWgT_hi + (size_t)NPG * KG, pWgT_lo + (size_t)NPG * KG,
        KG, KG / 4, NPG, nullptr, pgnnacc, nullptr, nullptr, nullptr, nullptr);
    k_epignn<<<gnnEpiBlocks, 256>>>(pgnnacc, gnn_b + D, ph2);

    // 4) entity pooling (-> hi/lo)
    k_ent<<<dim3(NE, B), 256>>>(ph1, ph2, e2m, e2m_mask, penthi, pentlo);

    // 5) linear halves of pair MLP (split-K z=5, atomic into entAB)
    k_zero<<<(entabN4 + 255) / 256, 256>>>(pentAB, entabN4);
    k_mm<128, 4><<<dim3((2 * HID) / 128, (B * NE) / 128, 5), 256, SMEM128>>>(
        penthi, pentlo, pW1linT_hi, pW1linT_lo, EE, EE / 5, 2 * HID, nullptr, pentAB,
        nullptr, nullptr, nullptr, nullptr);

    // 6) nonlinear pair features + big GEMM with fused gather epilogue -> hid hi/lo
    k_nl<<<dim3(P, B), 256>>>(penthi, pentlo, ent_pair, pnlhi, pnllo);
    k_mm<128, 2><<<dim3(HID / 128, (B * P) / 128, 1), 256, SMEM128>>>(
        pnlhi, pnllo, pW1nlT_hi, pW1nlT_lo, HID, HID, HID, b1, nullptr,
        phidhi, phidlo, pentAB, ent_pair);

    // 7) output layer: hidden @ W2 (split-K z=5, atomic), then +b2 epilogue
    k_zero<<<(outaccTotal / 4 + 255) / 256, 256>>>(poutacc, outaccTotal / 4);
    k_mm<64, 4><<<dim3(2, (B * P) / 128, 5), 256, SMEM64>>>(
        phidhi, phidlo, pW2T_hi, pW2T_lo, HID, HID / 5, OUT, nullptr, poutacc,
        nullptr, nullptr, nullptr, nullptr);
    k_epiout<<<(outaccTotal + 255) / 256, 256>>>(poutacc, b2, out, outaccTotal);
}